// round 7
// baseline (speedup 1.0000x reference)
#include <cuda_runtime.h>

#define MAXN 100000
#define MAXE 1600000
#define D    128

// ---------------- scratch (static __device__ — no allocations) ----------------
__device__ float g_bufA[(size_t)MAXN * D];   // H (GEMM output)
__device__ float g_bufB[(size_t)MAXN * D];   // agg layer1 (gemm2 input)
__device__ float g_bufC[(size_t)MAXN * D];   // agg layer2 (pool input)
__device__ float g_dinv[MAXN];
__device__ int   g_counts[MAXN];
__device__ int   g_cursor[MAXN];
__device__ int   g_rowptr[MAXN + 1];
__device__ int   g_bsums[128];
__device__ int2  g_epack[MAXE];              // (src col, weight bits)
__device__ int   g_src[MAXE];
__device__ int   g_dst[MAXE];
__device__ int   g_batch[MAXN];
__device__ int   g_is64;

// packed f32x2 FMA (Blackwell FFMA2 — only reachable via PTX fma.rn.f32x2)
#define FMA_F32X2(d, a, b) \
    asm("fma.rn.f32x2 %0, %1, %2, %0;" : "+l"(d) : "l"(a), "l"(b))

// ---------------- GEMM device body: H[tile rows] = X @ W (128x128) ----------------
// one block = 64 rows x 128 cols; thread = 4 rows x 8 cols (4 f32x2 pairs)
__device__ __forceinline__ void gemm_body(const float* __restrict__ X,
                                          const float* __restrict__ W,
                                          float* __restrict__ H,
                                          int tile, int N) {
    const int tid  = threadIdx.x;
    const int ry   = tid >> 4;          // 0..15
    const int cx   = tid & 15;          // 0..15
    const int row0 = tile * 64 + ry * 4;
    const int cb   = cx * 8;

    unsigned long long acc[4][4];
#pragma unroll
    for (int i = 0; i < 4; i++)
#pragma unroll
        for (int j = 0; j < 4; j++) acc[i][j] = 0ull;

    const float4* x4[4];
#pragma unroll
    for (int i = 0; i < 4; i++) {
        int r = row0 + i;
        if (r >= N) r = N - 1;          // clamp: safe address, masked on store
        x4[i] = reinterpret_cast<const float4*>(X + (size_t)r * D);
    }

    const unsigned long long* wp = reinterpret_cast<const unsigned long long*>(W + cb);

#pragma unroll 4
    for (int kc = 0; kc < 32; kc++) {
        float4 a0 = __ldg(x4[0] + kc);
        float4 a1 = __ldg(x4[1] + kc);
        float4 a2 = __ldg(x4[2] + kc);
        float4 a3 = __ldg(x4[3] + kc);
#pragma unroll
        for (int kk = 0; kk < 4; kk++) {
            unsigned long long w0, w1, w2, w3;
            asm("ld.global.nc.v2.u64 {%0,%1}, [%2];" : "=l"(w0), "=l"(w1) : "l"(wp));
            asm("ld.global.nc.v2.u64 {%0,%1}, [%2];" : "=l"(w2), "=l"(w3) : "l"(wp + 2));
            wp += 64;                   // next k row (512 B)
            float v0 = (kk == 0) ? a0.x : (kk == 1) ? a0.y : (kk == 2) ? a0.z : a0.w;
            float v1 = (kk == 0) ? a1.x : (kk == 1) ? a1.y : (kk == 2) ? a1.z : a1.w;
            float v2 = (kk == 0) ? a2.x : (kk == 1) ? a2.y : (kk == 2) ? a2.z : a2.w;
            float v3 = (kk == 0) ? a3.x : (kk == 1) ? a3.y : (kk == 2) ? a3.z : a3.w;
            unsigned long long p0, p1, p2, p3;
            asm("mov.b64 %0, {%1,%1};" : "=l"(p0) : "f"(v0));
            asm("mov.b64 %0, {%1,%1};" : "=l"(p1) : "f"(v1));
            asm("mov.b64 %0, {%1,%1};" : "=l"(p2) : "f"(v2));
            asm("mov.b64 %0, {%1,%1};" : "=l"(p3) : "f"(v3));
            FMA_F32X2(acc[0][0], p0, w0); FMA_F32X2(acc[0][1], p0, w1);
            FMA_F32X2(acc[0][2], p0, w2); FMA_F32X2(acc[0][3], p0, w3);
            FMA_F32X2(acc[1][0], p1, w0); FMA_F32X2(acc[1][1], p1, w1);
            FMA_F32X2(acc[1][2], p1, w2); FMA_F32X2(acc[1][3], p1, w3);
            FMA_F32X2(acc[2][0], p2, w0); FMA_F32X2(acc[2][1], p2, w1);
            FMA_F32X2(acc[2][2], p2, w2); FMA_F32X2(acc[2][3], p2, w3);
            FMA_F32X2(acc[3][0], p3, w0); FMA_F32X2(acc[3][1], p3, w1);
            FMA_F32X2(acc[3][2], p3, w2); FMA_F32X2(acc[3][3], p3, w3);
        }
    }

#pragma unroll
    for (int i = 0; i < 4; i++) {
        int r = row0 + i;
        if (r < N) {
            float o[8];
#pragma unroll
            for (int j = 0; j < 4; j++)
                asm("mov.b64 {%0,%1}, %2;" : "=f"(o[2*j]), "=f"(o[2*j+1]) : "l"(acc[i][j]));
            float* hp = H + (size_t)r * D + cb;
            *reinterpret_cast<float4*>(hp)     = make_float4(o[0], o[1], o[2], o[3]);
            *reinterpret_cast<float4*>(hp + 4) = make_float4(o[4], o[5], o[6], o[7]);
        }
    }
}

// ---------------- init: zero counts + dtype detect in one launch ----------------
// int64 indices < 100000: every odd 32-bit word is zero; impossible for random int32.
__global__ void k_init(const unsigned int* __restrict__ w, int N, int nodeB) {
    if (blockIdx.x < (unsigned)nodeB) {
        int i = blockIdx.x * 256 + threadIdx.x;
        if (i < N) g_counts[i] = 0;
    } else {
        __shared__ unsigned int s;
        if (threadIdx.x == 0) s = 0u;
        __syncthreads();
        unsigned int v = 0u;
        for (int i = threadIdx.x; i < 4096; i += 256) v |= w[2 * i + 1];
        atomicOr(&s, v);
        __syncthreads();
        if (threadIdx.x == 0) g_is64 = (s == 0u) ? 1 : 0;
    }
}

// ---------------- fatA: edge-convert + histogram + batch-convert  ||  gemm1 half1 ----------------
__global__ void __launch_bounds__(256) k_fatA(const void* __restrict__ edges,
                                              const void* __restrict__ batch,
                                              int E, int N, int PB,
                                              const float* __restrict__ X,
                                              const float* __restrict__ W,
                                              float* __restrict__ H) {
    if (blockIdx.x < (unsigned)PB) {
        int e = blockIdx.x * 256 + threadIdx.x;
        if (e < E) {
            int s, d;
            if (g_is64) {
                const long long* p = (const long long*)edges;
                s = (int)p[e]; d = (int)p[e + E];
            } else {
                const int* p = (const int*)edges;
                s = p[e]; d = p[e + E];
            }
            g_src[e] = s; g_dst[e] = d;
            atomicAdd(&g_counts[d], 1);
        }
        if (e < N) {
            if (g_is64) g_batch[e] = (int)((const long long*)batch)[e];
            else        g_batch[e] = ((const int*)batch)[e];
        }
    } else {
        gemm_body(X, W, H, blockIdx.x - PB, N);
    }
}

// ---------------- exclusive scan over counts (also emits dinv) ----------------
__global__ void k_scan_block(int N) {
    __shared__ int s[1024];
    int tid = threadIdx.x;
    int i = blockIdx.x * 1024 + tid;
    int v = (i < N) ? g_counts[i] : 0;
    if (i < N) g_dinv[i] = rsqrtf((float)v + 1.0f);
    s[tid] = v;
    __syncthreads();
    for (int off = 1; off < 1024; off <<= 1) {
        int t = (tid >= off) ? s[tid - off] : 0;
        __syncthreads();
        s[tid] += t;
        __syncthreads();
    }
    if (i < N) g_rowptr[i] = s[tid] - v;          // exclusive
    if (tid == 1023) g_bsums[blockIdx.x] = s[1023];
}

// scan of block sums done redundantly per block (nb <= 128), then add + cursor reset
__global__ void k_scan_add(int N, int E, int nb) {
    __shared__ int s[128];
    __shared__ int ex[128];
    int tid = threadIdx.x;
    if (tid < 128) {
        int v = (tid < nb) ? g_bsums[tid] : 0;
        s[tid] = v;
        ex[tid] = v;
    }
    __syncthreads();
    for (int off = 1; off < 128; off <<= 1) {
        int t = 0;
        if (tid < 128 && tid >= off) t = s[tid - off];
        __syncthreads();
        if (tid < 128) s[tid] += t;
        __syncthreads();
    }
    if (tid < 128) ex[tid] = s[tid] - ex[tid];    // exclusive
    __syncthreads();
    int i = blockIdx.x * 256 + tid;
    if (i < N) { g_rowptr[i] += ex[i >> 10]; g_cursor[i] = 0; }
    if (i == 0) g_rowptr[N] = E;
}

// ---------------- fatB: CSR fill  ||  gemm1 half2 ----------------
__global__ void __launch_bounds__(256) k_fatB(int E, int N, int FB, int tileOff,
                                              const float* __restrict__ X,
                                              const float* __restrict__ W,
                                              float* __restrict__ H) {
    if (blockIdx.x < (unsigned)FB) {
        int e = blockIdx.x * 256 + threadIdx.x;
        if (e < E) {
            int s = g_src[e], d = g_dst[e];
            int pos = atomicAdd(&g_cursor[d], 1);
            g_epack[g_rowptr[d] + pos] = make_int2(s, __float_as_int(g_dinv[s] * g_dinv[d]));
        }
    } else {
        gemm_body(X, W, H, tileOff + (int)blockIdx.x - FB, N);
    }
}

// ---------------- standalone GEMM (layer 2) ----------------
__global__ void __launch_bounds__(256) k_gemm(const float* __restrict__ X,
                                              const float* __restrict__ W,
                                              float* __restrict__ H, int N) {
    gemm_body(X, W, H, blockIdx.x, N);
}

// ---------------- gather: A[d] = selfterm + sum_e w[e]*H[src[e]]  (+bias,relu) ----------------
// one warp per dst node; lane owns a float4 (4 feats)
template <bool RELU>
__global__ void __launch_bounds__(256) k_gather(const float4* __restrict__ H4,
                                                float4* __restrict__ A4,
                                                const float* __restrict__ bias,
                                                int N) {
    int gw   = (blockIdx.x * blockDim.x + threadIdx.x) >> 5;
    int lane = threadIdx.x & 31;
    if (gw >= N) return;
    int beg = g_rowptr[gw], end = g_rowptr[gw + 1];

    float dv  = g_dinv[gw];
    float dv2 = dv * dv;
    float4 h  = H4[(size_t)gw * 32 + lane];
    float4 acc = make_float4(h.x * dv2, h.y * dv2, h.z * dv2, h.w * dv2);

    int j = beg;
    for (; j + 4 <= end; j += 4) {
        int2 m0 = __ldg(&g_epack[j]);
        int2 m1 = __ldg(&g_epack[j + 1]);
        int2 m2 = __ldg(&g_epack[j + 2]);
        int2 m3 = __ldg(&g_epack[j + 3]);
        float4 h0 = H4[(size_t)m0.x * 32 + lane];
        float4 h1 = H4[(size_t)m1.x * 32 + lane];
        float4 h2 = H4[(size_t)m2.x * 32 + lane];
        float4 h3 = H4[(size_t)m3.x * 32 + lane];
        float w0 = __int_as_float(m0.y), w1 = __int_as_float(m1.y);
        float w2 = __int_as_float(m2.y), w3 = __int_as_float(m3.y);
        acc.x = fmaf(h0.x, w0, acc.x); acc.y = fmaf(h0.y, w0, acc.y);
        acc.z = fmaf(h0.z, w0, acc.z); acc.w = fmaf(h0.w, w0, acc.w);
        acc.x = fmaf(h1.x, w1, acc.x); acc.y = fmaf(h1.y, w1, acc.y);
        acc.z = fmaf(h1.z, w1, acc.z); acc.w = fmaf(h1.w, w1, acc.w);
        acc.x = fmaf(h2.x, w2, acc.x); acc.y = fmaf(h2.y, w2, acc.y);
        acc.z = fmaf(h2.z, w2, acc.z); acc.w = fmaf(h2.w, w2, acc.w);
        acc.x = fmaf(h3.x, w3, acc.x); acc.y = fmaf(h3.y, w3, acc.y);
        acc.z = fmaf(h3.z, w3, acc.z); acc.w = fmaf(h3.w, w3, acc.w);
    }
    for (; j < end; j++) {
        int2 m = __ldg(&g_epack[j]);
        float4 hh = H4[(size_t)m.x * 32 + lane];
        float w = __int_as_float(m.y);
        acc.x = fmaf(hh.x, w, acc.x); acc.y = fmaf(hh.y, w, acc.y);
        acc.z = fmaf(hh.z, w, acc.z); acc.w = fmaf(hh.w, w, acc.w);
    }

    if (RELU) {
        float4 bb = reinterpret_cast<const float4*>(bias)[lane];
        acc.x = fmaxf(acc.x + bb.x, 0.0f);
        acc.y = fmaxf(acc.y + bb.y, 0.0f);
        acc.z = fmaxf(acc.z + bb.z, 0.0f);
        acc.w = fmaxf(acc.w + bb.w, 0.0f);
    }
    A4[(size_t)gw * 32 + lane] = acc;
}

// ---------------- fused global-mean-pool (+b2,relu) + MLP head ----------------
__global__ void __launch_bounds__(128) k_pool_mlp(const float* __restrict__ AGG,
                                                  const float* __restrict__ b2,
                                                  int Nnodes,
                                                  const float* __restrict__ Wm1,
                                                  const float* __restrict__ bm1,
                                                  const float* __restrict__ Wm2,
                                                  const float* __restrict__ bm2,
                                                  const float* __restrict__ Wm3,
                                                  const float* __restrict__ bm3,
                                                  float* __restrict__ out) {
    const int g = blockIdx.x;
    const int tid = threadIdx.x;
    __shared__ int sb[2];
    __shared__ float gs[128];
    __shared__ float a1[500];
    __shared__ float a2[100];
    __shared__ float red[128];

    if (tid < 2) {
        int target = g + tid;
        int lo = 0, hi = Nnodes;
        while (lo < hi) {
            int mid = (lo + hi) >> 1;
            if (g_batch[mid] < target) lo = mid + 1; else hi = mid;
        }
        sb[tid] = lo;
    }
    __syncthreads();
    int beg = sb[0], end = sb[1];
    int cnt = end - beg;

    float bb = b2[tid];
    float sum = 0.0f;
#pragma unroll 4
    for (int n = beg; n < end; n++)
        sum += fmaxf(AGG[(size_t)n * D + tid] + bb, 0.0f);
    gs[tid] = sum / (float)max(cnt, 1);
    __syncthreads();

    for (int o = tid; o < 500; o += 128) {
        float acc = bm1[o];
#pragma unroll 4
        for (int j = 0; j < 128; j++)
            acc = fmaf(gs[j], Wm1[j * 500 + o], acc);
        a1[o] = fmaxf(acc, 0.0f);
    }
    __syncthreads();

    if (tid < 100) {
        float acc = bm2[tid];
        for (int j = 0; j < 500; j++)
            acc = fmaf(a1[j], Wm2[j * 100 + tid], acc);
        a2[tid] = fmaxf(acc, 0.0f);
    }
    __syncthreads();

    red[tid] = (tid < 100) ? a2[tid] * Wm3[tid] : 0.0f;
    __syncthreads();
    for (int s = 64; s > 0; s >>= 1) {
        if (tid < s) red[tid] += red[tid + s];
        __syncthreads();
    }
    if (tid == 0) out[g] = red[0] + bm3[0];
}

// ---------------- launch ----------------
extern "C" void kernel_launch(void* const* d_in, const int* in_sizes, int n_in,
                              void* d_out, int out_size) {
    const float* x     = (const float*)d_in[0];
    const void*  edges = d_in[1];
    const void*  batch = d_in[2];
    const float* W1  = (const float*)d_in[3];
    const float* b1  = (const float*)d_in[4];
    const float* W2  = (const float*)d_in[5];
    const float* b2  = (const float*)d_in[6];
    const float* Wm1 = (const float*)d_in[7];
    const float* bm1 = (const float*)d_in[8];
    const float* Wm2 = (const float*)d_in[9];
    const float* bm2 = (const float*)d_in[10];
    const float* Wm3 = (const float*)d_in[11];
    const float* bm3 = (const float*)d_in[12];
    float* out = (float*)d_out;

    const int N = in_sizes[0] / D;
    const int E = in_sizes[1] / 2;
    const int G = out_size;

    float *bufA = nullptr, *bufB = nullptr, *bufC = nullptr;
    cudaGetSymbolAddress((void**)&bufA, g_bufA);
    cudaGetSymbolAddress((void**)&bufB, g_bufB);
    cudaGetSymbolAddress((void**)&bufC, g_bufC);

    const int tB = 256;
    const int nodeB  = (N + tB - 1) / tB;
    const int PB     = (E + tB - 1) / tB;          // prep/fill blocks
    const int scanNb = (N + 1023) / 1024;
    const int tiles  = (N + 63) / 64;
    const int half1  = (tiles + 1) / 2;
    const int half2  = tiles - half1;
    const int warpB  = (N * 32 + tB - 1) / tB;     // 1 warp/node

    // 0: zero counts + detect dtype
    k_init<<<nodeB + 1, tB>>>((const unsigned int*)edges, N, nodeB);
    // 1: edge prep + histogram + batch convert  ||  gemm1 half1  (independent work)
    k_fatA<<<PB + half1, tB>>>(edges, batch, E, N, PB, x, W1, bufA);
    // 2,3: rowptr exclusive scan (+dinv, cursor reset)
    k_scan_block<<<scanNb, 1024>>>(N);
    k_scan_add<<<nodeB, tB>>>(N, E, scanNb);
    // 4: CSR fill  ||  gemm1 half2
    k_fatB<<<PB + half2, tB>>>(E, N, PB, half1, x, W1, bufA);
    // 5: layer1 aggregate + bias + relu
    k_gather<true><<<warpB, tB>>>((const float4*)bufA, (float4*)bufB, b1, N);
    // 6: layer2 GEMM
    k_gemm<<<tiles, tB>>>(bufB, W2, bufA, N);
    // 7: layer2 aggregate
    k_gather<false><<<warpB, tB>>>((const float4*)bufA, (float4*)bufC, nullptr, N);
    // 8: pool + MLP head (applies b2 + relu)
    k_pool_mlp<<<G, 128>>>(bufC, b2, N, Wm1, bm1, Wm2, bm2, Wm3, bm3, out);
}

// round 8
// speedup vs baseline: 1.0543x; 1.0543x over previous
#include <cuda_runtime.h>

#define MAXN 100000
#define MAXE 1600000
#define D    128

// ---------------- scratch (static __device__ — no allocations) ----------------
__device__ float g_bufA[(size_t)MAXN * D];   // H (GEMM output)
__device__ float g_bufB[(size_t)MAXN * D];   // H2 (fused gather+gemm2 output)
__device__ float g_bufC[(size_t)MAXN * D];   // agg layer2 (pool input)
__device__ float g_dinv[MAXN];
__device__ int   g_counts[MAXN];
__device__ int   g_cursor[MAXN];
__device__ int   g_rowptr[MAXN + 1];
__device__ int   g_bsums[128];
__device__ int2  g_epack[MAXE];              // (src col, weight bits)
__device__ int   g_batch[MAXN];
__device__ int   g_is64;

// packed f32x2 FMA (Blackwell FFMA2 — only reachable via PTX fma.rn.f32x2)
#define FMA_F32X2(d, a, b) \
    asm("fma.rn.f32x2 %0, %1, %2, %0;" : "+l"(d) : "l"(a), "l"(b))

// ---------------- init: zero counts + dtype detect ----------------
// int64 indices < 100000: every odd 32-bit word is zero; impossible for random int32.
__global__ void k_init(const unsigned int* __restrict__ w, int N, int nodeB) {
    if (blockIdx.x < (unsigned)nodeB) {
        int i = blockIdx.x * 256 + threadIdx.x;
        if (i < N) g_counts[i] = 0;
    } else {
        __shared__ unsigned int s;
        if (threadIdx.x == 0) s = 0u;
        __syncthreads();
        unsigned int v = 0u;
        for (int i = threadIdx.x; i < 4096; i += 256) v |= w[2 * i + 1];
        atomicOr(&s, v);
        __syncthreads();
        if (threadIdx.x == 0) g_is64 = (s == 0u) ? 1 : 0;
    }
}

// ---------------- degree histogram (dst read straight from edges) + batch convert ----------------
__global__ void k_prep(const void* __restrict__ edges, const void* __restrict__ batch,
                       int E, int N) {
    int e = blockIdx.x * blockDim.x + threadIdx.x;
    if (e < E) {
        int d;
        if (g_is64) d = (int)((const long long*)edges)[e + E];
        else        d = ((const int*)edges)[e + E];
        atomicAdd(&g_counts[d], 1);
    }
    if (e < N) {
        if (g_is64) g_batch[e] = (int)((const long long*)batch)[e];
        else        g_batch[e] = ((const int*)batch)[e];
    }
}

// ---------------- exclusive scan over counts (also emits dinv) ----------------
__global__ void k_scan_block(int N) {
    __shared__ int s[1024];
    int tid = threadIdx.x;
    int i = blockIdx.x * 1024 + tid;
    int v = (i < N) ? g_counts[i] : 0;
    if (i < N) g_dinv[i] = rsqrtf((float)v + 1.0f);
    s[tid] = v;
    __syncthreads();
    for (int off = 1; off < 1024; off <<= 1) {
        int t = (tid >= off) ? s[tid - off] : 0;
        __syncthreads();
        s[tid] += t;
        __syncthreads();
    }
    if (i < N) g_rowptr[i] = s[tid] - v;          // exclusive
    if (tid == 1023) g_bsums[blockIdx.x] = s[1023];
}

// block-sums scanned redundantly per block (nb <= 128), then add + cursor reset
__global__ void k_scan_add(int N, int E, int nb) {
    __shared__ int s[128];
    __shared__ int ex[128];
    int tid = threadIdx.x;
    if (tid < 128) {
        int v = (tid < nb) ? g_bsums[tid] : 0;
        s[tid] = v;
        ex[tid] = v;
    }
    __syncthreads();
    for (int off = 1; off < 128; off <<= 1) {
        int t = 0;
        if (tid < 128 && tid >= off) t = s[tid - off];
        __syncthreads();
        if (tid < 128) s[tid] += t;
        __syncthreads();
    }
    if (tid < 128) ex[tid] = s[tid] - ex[tid];    // exclusive
    __syncthreads();
    int i = blockIdx.x * 256 + tid;
    if (i < N) { g_rowptr[i] += ex[i >> 10]; g_cursor[i] = 0; }
    if (i == 0) g_rowptr[N] = E;
}

// ---------------- CSR fill (src/dst read straight from edges) ----------------
__global__ void k_fill(const void* __restrict__ edges, int E) {
    int e = blockIdx.x * blockDim.x + threadIdx.x;
    if (e >= E) return;
    int s, d;
    if (g_is64) {
        const long long* p = (const long long*)edges;
        s = (int)p[e]; d = (int)p[e + E];
    } else {
        const int* p = (const int*)edges;
        s = p[e]; d = p[e + E];
    }
    int pos = atomicAdd(&g_cursor[d], 1);
    g_epack[g_rowptr[d] + pos] = make_int2(s, __float_as_int(g_dinv[s] * g_dinv[d]));
}

// ---------------- GEMM: H = X @ W via packed f32x2 FMA (A from global) ----------------
// one block = 64 rows x 128 cols; thread = 4 rows x 8 cols (4 f32x2 pairs)
__global__ void __launch_bounds__(256) k_gemm(const float* __restrict__ X,
                                              const float* __restrict__ W,
                                              float* __restrict__ H, int N) {
    const int tid  = threadIdx.x;
    const int ry   = tid >> 4;
    const int cx   = tid & 15;
    const int row0 = blockIdx.x * 64 + ry * 4;
    const int cb   = cx * 8;

    unsigned long long acc[4][4];
#pragma unroll
    for (int i = 0; i < 4; i++)
#pragma unroll
        for (int j = 0; j < 4; j++) acc[i][j] = 0ull;

    const float4* x4[4];
#pragma unroll
    for (int i = 0; i < 4; i++) {
        int r = row0 + i;
        if (r >= N) r = N - 1;          // clamp: safe address, masked on store
        x4[i] = reinterpret_cast<const float4*>(X + (size_t)r * D);
    }

    const unsigned long long* wp = reinterpret_cast<const unsigned long long*>(W + cb);

#pragma unroll 4
    for (int kc = 0; kc < 32; kc++) {
        float4 a0 = __ldg(x4[0] + kc);
        float4 a1 = __ldg(x4[1] + kc);
        float4 a2 = __ldg(x4[2] + kc);
        float4 a3 = __ldg(x4[3] + kc);
#pragma unroll
        for (int kk = 0; kk < 4; kk++) {
            unsigned long long w0, w1, w2, w3;
            asm("ld.global.nc.v2.u64 {%0,%1}, [%2];" : "=l"(w0), "=l"(w1) : "l"(wp));
            asm("ld.global.nc.v2.u64 {%0,%1}, [%2];" : "=l"(w2), "=l"(w3) : "l"(wp + 2));
            wp += 64;
            float v0 = (kk == 0) ? a0.x : (kk == 1) ? a0.y : (kk == 2) ? a0.z : a0.w;
            float v1 = (kk == 0) ? a1.x : (kk == 1) ? a1.y : (kk == 2) ? a1.z : a1.w;
            float v2 = (kk == 0) ? a2.x : (kk == 1) ? a2.y : (kk == 2) ? a2.z : a2.w;
            float v3 = (kk == 0) ? a3.x : (kk == 1) ? a3.y : (kk == 2) ? a3.z : a3.w;
            unsigned long long p0, p1, p2, p3;
            asm("mov.b64 %0, {%1,%1};" : "=l"(p0) : "f"(v0));
            asm("mov.b64 %0, {%1,%1};" : "=l"(p1) : "f"(v1));
            asm("mov.b64 %0, {%1,%1};" : "=l"(p2) : "f"(v2));
            asm("mov.b64 %0, {%1,%1};" : "=l"(p3) : "f"(v3));
            FMA_F32X2(acc[0][0], p0, w0); FMA_F32X2(acc[0][1], p0, w1);
            FMA_F32X2(acc[0][2], p0, w2); FMA_F32X2(acc[0][3], p0, w3);
            FMA_F32X2(acc[1][0], p1, w0); FMA_F32X2(acc[1][1], p1, w1);
            FMA_F32X2(acc[1][2], p1, w2); FMA_F32X2(acc[1][3], p1, w3);
            FMA_F32X2(acc[2][0], p2, w0); FMA_F32X2(acc[2][1], p2, w1);
            FMA_F32X2(acc[2][2], p2, w2); FMA_F32X2(acc[2][3], p2, w3);
            FMA_F32X2(acc[3][0], p3, w0); FMA_F32X2(acc[3][1], p3, w1);
            FMA_F32X2(acc[3][2], p3, w2); FMA_F32X2(acc[3][3], p3, w3);
        }
    }

#pragma unroll
    for (int i = 0; i < 4; i++) {
        int r = row0 + i;
        if (r < N) {
            float o[8];
#pragma unroll
            for (int j = 0; j < 4; j++)
                asm("mov.b64 {%0,%1}, %2;" : "=f"(o[2*j]), "=f"(o[2*j+1]) : "l"(acc[i][j]));
            float* hp = H + (size_t)r * D + cb;
            *reinterpret_cast<float4*>(hp)     = make_float4(o[0], o[1], o[2], o[3]);
            *reinterpret_cast<float4*>(hp + 4) = make_float4(o[4], o[5], o[6], o[7]);
        }
    }
}

// ---------------- gather helper: A[d] row (lane's float4), self-term + edges ----------------
__device__ __forceinline__ float4 gather_row(const float4* __restrict__ H4,
                                             int node, int lane) {
    int beg = g_rowptr[node], end = g_rowptr[node + 1];
    float dv  = g_dinv[node];
    float dv2 = dv * dv;
    float4 h  = H4[(size_t)node * 32 + lane];
    float4 acc = make_float4(h.x * dv2, h.y * dv2, h.z * dv2, h.w * dv2);

    int j = beg;
    for (; j + 4 <= end; j += 4) {
        int2 m0 = __ldg(&g_epack[j]);
        int2 m1 = __ldg(&g_epack[j + 1]);
        int2 m2 = __ldg(&g_epack[j + 2]);
        int2 m3 = __ldg(&g_epack[j + 3]);
        float4 h0 = H4[(size_t)m0.x * 32 + lane];
        float4 h1 = H4[(size_t)m1.x * 32 + lane];
        float4 h2 = H4[(size_t)m2.x * 32 + lane];
        float4 h3 = H4[(size_t)m3.x * 32 + lane];
        float w0 = __int_as_float(m0.y), w1 = __int_as_float(m1.y);
        float w2 = __int_as_float(m2.y), w3 = __int_as_float(m3.y);
        acc.x = fmaf(h0.x, w0, acc.x); acc.y = fmaf(h0.y, w0, acc.y);
        acc.z = fmaf(h0.z, w0, acc.z); acc.w = fmaf(h0.w, w0, acc.w);
        acc.x = fmaf(h1.x, w1, acc.x); acc.y = fmaf(h1.y, w1, acc.y);
        acc.z = fmaf(h1.z, w1, acc.z); acc.w = fmaf(h1.w, w1, acc.w);
        acc.x = fmaf(h2.x, w2, acc.x); acc.y = fmaf(h2.y, w2, acc.y);
        acc.z = fmaf(h2.z, w2, acc.z); acc.w = fmaf(h2.w, w2, acc.w);
        acc.x = fmaf(h3.x, w3, acc.x); acc.y = fmaf(h3.y, w3, acc.y);
        acc.z = fmaf(h3.z, w3, acc.z); acc.w = fmaf(h3.w, w3, acc.w);
    }
    for (; j < end; j++) {
        int2 m = __ldg(&g_epack[j]);
        float4 hh = H4[(size_t)m.x * 32 + lane];
        float w = __int_as_float(m.y);
        acc.x = fmaf(hh.x, w, acc.x); acc.y = fmaf(hh.y, w, acc.y);
        acc.z = fmaf(hh.z, w, acc.z); acc.w = fmaf(hh.w, w, acc.w);
    }
    return acc;
}

// ---------------- fused: (gather1 + b1 + relu) -> smem tile -> gemm2 -> H2 ----------------
// block = 64 dst nodes; smem A tile padded to 132 floats/row (conflict-free)
__global__ void __launch_bounds__(256) k_fused_ag(const float4* __restrict__ H4,
                                                  const float* __restrict__ bias,
                                                  const float* __restrict__ W,
                                                  float* __restrict__ H2, int N) {
    __shared__ float s_a[64 * 132];
    const int tid  = threadIdx.x;
    const int wid  = tid >> 5;
    const int lane = tid & 31;
    const int tile = blockIdx.x;

    float4 bb = reinterpret_cast<const float4*>(bias)[lane];

    // phase 1: 8 warps gather 8 nodes each into smem (bias+relu applied)
#pragma unroll
    for (int i = 0; i < 8; i++) {
        int lrow = wid * 8 + i;
        int node = tile * 64 + lrow;
        float4 v;
        if (node < N) {
            float4 acc = gather_row(H4, node, lane);
            v = make_float4(fmaxf(acc.x + bb.x, 0.0f), fmaxf(acc.y + bb.y, 0.0f),
                            fmaxf(acc.z + bb.z, 0.0f), fmaxf(acc.w + bb.w, 0.0f));
        } else {
            v = make_float4(0.0f, 0.0f, 0.0f, 0.0f);
        }
        *reinterpret_cast<float4*>(&s_a[lrow * 132 + lane * 4]) = v;
    }
    __syncthreads();

    // phase 2: GEMM from smem
    const int ry   = tid >> 4;
    const int cx   = tid & 15;
    const int row0 = ry * 4;
    const int cb   = cx * 8;

    unsigned long long acc[4][4];
#pragma unroll
    for (int i = 0; i < 4; i++)
#pragma unroll
        for (int j = 0; j < 4; j++) acc[i][j] = 0ull;

    const unsigned long long* wp = reinterpret_cast<const unsigned long long*>(W + cb);

#pragma unroll 4
    for (int kc = 0; kc < 32; kc++) {
        float4 a0 = *reinterpret_cast<const float4*>(&s_a[(row0 + 0) * 132 + kc * 4]);
        float4 a1 = *reinterpret_cast<const float4*>(&s_a[(row0 + 1) * 132 + kc * 4]);
        float4 a2 = *reinterpret_cast<const float4*>(&s_a[(row0 + 2) * 132 + kc * 4]);
        float4 a3 = *reinterpret_cast<const float4*>(&s_a[(row0 + 3) * 132 + kc * 4]);
#pragma unroll
        for (int kk = 0; kk < 4; kk++) {
            unsigned long long w0, w1, w2, w3;
            asm("ld.global.nc.v2.u64 {%0,%1}, [%2];" : "=l"(w0), "=l"(w1) : "l"(wp));
            asm("ld.global.nc.v2.u64 {%0,%1}, [%2];" : "=l"(w2), "=l"(w3) : "l"(wp + 2));
            wp += 64;
            float v0 = (kk == 0) ? a0.x : (kk == 1) ? a0.y : (kk == 2) ? a0.z : a0.w;
            float v1 = (kk == 0) ? a1.x : (kk == 1) ? a1.y : (kk == 2) ? a1.z : a1.w;
            float v2 = (kk == 0) ? a2.x : (kk == 1) ? a2.y : (kk == 2) ? a2.z : a2.w;
            float v3 = (kk == 0) ? a3.x : (kk == 1) ? a3.y : (kk == 2) ? a3.z : a3.w;
            unsigned long long p0, p1, p2, p3;
            asm("mov.b64 %0, {%1,%1};" : "=l"(p0) : "f"(v0));
            asm("mov.b64 %0, {%1,%1};" : "=l"(p1) : "f"(v1));
            asm("mov.b64 %0, {%1,%1};" : "=l"(p2) : "f"(v2));
            asm("mov.b64 %0, {%1,%1};" : "=l"(p3) : "f"(v3));
            FMA_F32X2(acc[0][0], p0, w0); FMA_F32X2(acc[0][1], p0, w1);
            FMA_F32X2(acc[0][2], p0, w2); FMA_F32X2(acc[0][3], p0, w3);
            FMA_F32X2(acc[1][0], p1, w0); FMA_F32X2(acc[1][1], p1, w1);
            FMA_F32X2(acc[1][2], p1, w2); FMA_F32X2(acc[1][3], p1, w3);
            FMA_F32X2(acc[2][0], p2, w0); FMA_F32X2(acc[2][1], p2, w1);
            FMA_F32X2(acc[2][2], p2, w2); FMA_F32X2(acc[2][3], p2, w3);
            FMA_F32X2(acc[3][0], p3, w0); FMA_F32X2(acc[3][1], p3, w1);
            FMA_F32X2(acc[3][2], p3, w2); FMA_F32X2(acc[3][3], p3, w3);
        }
    }

#pragma unroll
    for (int i = 0; i < 4; i++) {
        int r = tile * 64 + row0 + i;
        if (r < N) {
            float o[8];
#pragma unroll
            for (int j = 0; j < 4; j++)
                asm("mov.b64 {%0,%1}, %2;" : "=f"(o[2*j]), "=f"(o[2*j+1]) : "l"(acc[i][j]));
            float* hp = H2 + (size_t)r * D + cb;
            *reinterpret_cast<float4*>(hp)     = make_float4(o[0], o[1], o[2], o[3]);
            *reinterpret_cast<float4*>(hp + 4) = make_float4(o[4], o[5], o[6], o[7]);
        }
    }
}

// ---------------- standalone gather (layer 2, no relu/bias) ----------------
__global__ void __launch_bounds__(256) k_gather2(const float4* __restrict__ H4,
                                                 float4* __restrict__ A4, int N) {
    int gw   = (blockIdx.x * blockDim.x + threadIdx.x) >> 5;
    int lane = threadIdx.x & 31;
    if (gw >= N) return;
    A4[(size_t)gw * 32 + lane] = gather_row(H4, gw, lane);
}

// ---------------- fused global-mean-pool (+b2,relu) + MLP head ----------------
__global__ void __launch_bounds__(128) k_pool_mlp(const float* __restrict__ AGG,
                                                  const float* __restrict__ b2,
                                                  int Nnodes,
                                                  const float* __restrict__ Wm1,
                                                  const float* __restrict__ bm1,
                                                  const float* __restrict__ Wm2,
                                                  const float* __restrict__ bm2,
                                                  const float* __restrict__ Wm3,
                                                  const float* __restrict__ bm3,
                                                  float* __restrict__ out) {
    const int g = blockIdx.x;
    const int tid = threadIdx.x;
    __shared__ int sb[2];
    __shared__ float gs[128];
    __shared__ float a1[500];
    __shared__ float a2[100];
    __shared__ float red[128];

    if (tid < 2) {
        int target = g + tid;
        int lo = 0, hi = Nnodes;
        while (lo < hi) {
            int mid = (lo + hi) >> 1;
            if (g_batch[mid] < target) lo = mid + 1; else hi = mid;
        }
        sb[tid] = lo;
    }
    __syncthreads();
    int beg = sb[0], end = sb[1];
    int cnt = end - beg;

    float bb = b2[tid];
    float sum = 0.0f;
#pragma unroll 4
    for (int n = beg; n < end; n++)
        sum += fmaxf(AGG[(size_t)n * D + tid] + bb, 0.0f);
    gs[tid] = sum / (float)max(cnt, 1);
    __syncthreads();

    for (int o = tid; o < 500; o += 128) {
        float acc = bm1[o];
#pragma unroll 4
        for (int j = 0; j < 128; j++)
            acc = fmaf(gs[j], Wm1[j * 500 + o], acc);
        a1[o] = fmaxf(acc, 0.0f);
    }
    __syncthreads();

    if (tid < 100) {
        float acc = bm2[tid];
        for (int j = 0; j < 500; j++)
            acc = fmaf(a1[j], Wm2[j * 100 + tid], acc);
        a2[tid] = fmaxf(acc, 0.0f);
    }
    __syncthreads();

    red[tid] = (tid < 100) ? a2[tid] * Wm3[tid] : 0.0f;
    __syncthreads();
    for (int s = 64; s > 0; s >>= 1) {
        if (tid < s) red[tid] += red[tid + s];
        __syncthreads();
    }
    if (tid == 0) out[g] = red[0] + bm3[0];
}

// ---------------- launch ----------------
extern "C" void kernel_launch(void* const* d_in, const int* in_sizes, int n_in,
                              void* d_out, int out_size) {
    const float* x     = (const float*)d_in[0];
    const void*  edges = d_in[1];
    const void*  batch = d_in[2];
    const float* W1  = (const float*)d_in[3];
    const float* b1  = (const float*)d_in[4];
    const float* W2  = (const float*)d_in[5];
    const float* b2  = (const float*)d_in[6];
    const float* Wm1 = (const float*)d_in[7];
    const float* bm1 = (const float*)d_in[8];
    const float* Wm2 = (const float*)d_in[9];
    const float* bm2 = (const float*)d_in[10];
    const float* Wm3 = (const float*)d_in[11];
    const float* bm3 = (const float*)d_in[12];
    float* out = (float*)d_out;

    const int N = in_sizes[0] / D;
    const int E = in_sizes[1] / 2;
    const int G = out_size;

    float *bufA = nullptr, *bufB = nullptr, *bufC = nullptr;
    cudaGetSymbolAddress((void**)&bufA, g_bufA);
    cudaGetSymbolAddress((void**)&bufB, g_bufB);
    cudaGetSymbolAddress((void**)&bufC, g_bufC);

    const int tB = 256;
    const int nodeB  = (N + tB - 1) / tB;
    const int edgeB  = (E + tB - 1) / tB;
    const int scanNb = (N + 1023) / 1024;
    const int tiles  = (N + 63) / 64;
    const int warpB  = (N * 32 + tB - 1) / tB;     // 1 warp/node

    // 0: zero counts + detect dtype
    k_init<<<nodeB + 1, tB>>>((const unsigned int*)edges, N, nodeB);
    // 1: degree histogram + batch convert
    k_prep<<<edgeB, tB>>>(edges, batch, E, N);
    // 2: rowptr scan part 1
    k_scan_block<<<scanNb, 1024>>>(N);
    // 3: layer1 GEMM (independent of CSR) — ncu capture slot
    k_gemm<<<tiles, tB>>>(x, W1, bufA, N);
    // 4: rowptr scan part 2 (+dinv consumers, cursor reset)
    k_scan_add<<<nodeB, tB>>>(N, E, scanNb);
    // 5: CSR fill
    k_fill<<<edgeB, tB>>>(edges, E);
    // 6: fused gather1+b1+relu -> gemm2
    k_fused_ag<<<tiles, tB>>>((const float4*)bufA, b1, W2, bufB, N);
    // 7: layer2 aggregate
    k_gather2<<<warpB, tB>>>((const float4*)bufB, (float4*)bufC, N);
    // 8: pool + MLP head (applies b2 + relu)
    k_pool_mlp<<<G, 128>>>(bufC, b2, N, Wm1, bm1, Wm2, bm2, Wm3, bm3, out);
}

// round 12
// speedup vs baseline: 1.1354x; 1.0769x over previous
#include <cuda_runtime.h>

#define MAXN 100000
#define MAXE 1600000
#define D    128

// ---------------- scratch (static __device__ — no allocations) ----------------
__device__ float g_bufA[(size_t)MAXN * D];   // H (GEMM output)
__device__ float g_bufB[(size_t)MAXN * D];   // H2 (fused gather+gemm2 output)
__device__ float g_bufC[(size_t)MAXN * D];   // agg layer2 (pool input)
__device__ float g_dinv[MAXN];
__device__ int   g_counts[MAXN];
__device__ int   g_cursor[MAXN];
__device__ int   g_rowptr[MAXN + 1];
__device__ int   g_bsums[128];
__device__ int2  g_epack[MAXE];              // (src col, weight bits)
__device__ int   g_batch[MAXN];
__device__ int   g_is64;

// packed f32x2 FMA (Blackwell FFMA2 — only reachable via PTX fma.rn.f32x2)
#define FMA_F32X2(d, a, b) \
    asm("fma.rn.f32x2 %0, %1, %2, %0;" : "+l"(d) : "l"(a), "l"(b))

// ---------------- init: zero counts + dtype detect ----------------
// int64 indices < 100000: every odd 32-bit word is zero; impossible for random int32.
__global__ void k_init(const unsigned int* __restrict__ w, int N, int nodeB) {
    if (blockIdx.x < (unsigned)nodeB) {
        int i = blockIdx.x * 256 + threadIdx.x;
        if (i < N) g_counts[i] = 0;
    } else {
        __shared__ unsigned int s;
        if (threadIdx.x == 0) s = 0u;
        __syncthreads();
        unsigned int v = 0u;
        for (int i = threadIdx.x; i < 4096; i += 256) v |= w[2 * i + 1];
        atomicOr(&s, v);
        __syncthreads();
        if (threadIdx.x == 0) g_is64 = (s == 0u) ? 1 : 0;
    }
}

// ---------------- degree histogram + batch convert ----------------
__global__ void k_prep(const void* __restrict__ edges, const void* __restrict__ batch,
                       int E, int N) {
    int e = blockIdx.x * blockDim.x + threadIdx.x;
    if (e < E) {
        int d;
        if (g_is64) d = (int)((const long long*)edges)[e + E];
        else        d = ((const int*)edges)[e + E];
        atomicAdd(&g_counts[d], 1);
    }
    if (e < N) {
        if (g_is64) g_batch[e] = (int)((const long long*)batch)[e];
        else        g_batch[e] = ((const int*)batch)[e];
    }
}

// ---------------- exclusive scan over counts (also emits dinv) ----------------
__global__ void k_scan_block(int N) {
    __shared__ int s[1024];
    int tid = threadIdx.x;
    int i = blockIdx.x * 1024 + tid;
    int v = (i < N) ? g_counts[i] : 0;
    if (i < N) g_dinv[i] = rsqrtf((float)v + 1.0f);
    s[tid] = v;
    __syncthreads();
    for (int off = 1; off < 1024; off <<= 1) {
        int t = (tid >= off) ? s[tid - off] : 0;
        __syncthreads();
        s[tid] += t;
        __syncthreads();
    }
    if (i < N) g_rowptr[i] = s[tid] - v;          // exclusive
    if (tid == 1023) g_bsums[blockIdx.x] = s[1023];
}

// block-sums scanned redundantly per block (nb <= 128), then add + cursor reset
__global__ void k_scan_add(int N, int E, int nb) {
    __shared__ int s[128];
    __shared__ int ex[128];
    int tid = threadIdx.x;
    if (tid < 128) {
        int v = (tid < nb) ? g_bsums[tid] : 0;
        s[tid] = v;
        ex[tid] = v;
    }
    __syncthreads();
    for (int off = 1; off < 128; off <<= 1) {
        int t = 0;
        if (tid < 128 && tid >= off) t = s[tid - off];
        __syncthreads();
        if (tid < 128) s[tid] += t;
        __syncthreads();
    }
    if (tid < 128) ex[tid] = s[tid] - ex[tid];    // exclusive
    __syncthreads();
    int i = blockIdx.x * 256 + tid;
    if (i < N) { g_rowptr[i] += ex[i >> 10]; g_cursor[i] = 0; }
    if (i == 0) g_rowptr[N] = E;
}

// ---------------- CSR fill ----------------
__global__ void k_fill(const void* __restrict__ edges, int E) {
    int e = blockIdx.x * blockDim.x + threadIdx.x;
    if (e >= E) return;
    int s, d;
    if (g_is64) {
        const long long* p = (const long long*)edges;
        s = (int)p[e]; d = (int)p[e + E];
    } else {
        const int* p = (const int*)edges;
        s = p[e]; d = p[e + E];
    }
    int pos = atomicAdd(&g_cursor[d], 1);
    g_epack[g_rowptr[d] + pos] = make_int2(s, __float_as_int(g_dinv[s] * g_dinv[d]));
}

// ---------------- GEMM inner: 8 rows x 8 cols per thread, W from global (.nc) ----------------
#define GEMM_INNER(LOAD_A)                                                        \
    unsigned long long acc[8][4];                                                 \
    _Pragma("unroll")                                                             \
    for (int i = 0; i < 8; i++)                                                   \
        _Pragma("unroll")                                                         \
        for (int j = 0; j < 4; j++) acc[i][j] = 0ull;                             \
    const unsigned long long* wp = reinterpret_cast<const unsigned long long*>(W + cb); \
    _Pragma("unroll 2")                                                           \
    for (int kc = 0; kc < 32; kc++) {                                             \
        float4 a[8];                                                              \
        _Pragma("unroll")                                                         \
        for (int i = 0; i < 8; i++) a[i] = LOAD_A(i);                             \
        _Pragma("unroll")                                                         \
        for (int kk = 0; kk < 4; kk++) {                                          \
            unsigned long long w0, w1, w2, w3;                                    \
            asm("ld.global.nc.v2.u64 {%0,%1}, [%2];" : "=l"(w0), "=l"(w1) : "l"(wp));     \
            asm("ld.global.nc.v2.u64 {%0,%1}, [%2];" : "=l"(w2), "=l"(w3) : "l"(wp + 2)); \
            wp += 64;                                                             \
            _Pragma("unroll")                                                     \
            for (int i = 0; i < 8; i++) {                                         \
                float v = (kk == 0) ? a[i].x : (kk == 1) ? a[i].y                 \
                        : (kk == 2) ? a[i].z : a[i].w;                            \
                unsigned long long p;                                             \
                asm("mov.b64 %0, {%1,%1};" : "=l"(p) : "f"(v));                   \
                FMA_F32X2(acc[i][0], p, w0); FMA_F32X2(acc[i][1], p, w1);         \
                FMA_F32X2(acc[i][2], p, w2); FMA_F32X2(acc[i][3], p, w3);         \
            }                                                                     \
        }                                                                         \
    }

#define GEMM_STORE(H2, ROWBASE)                                                   \
    _Pragma("unroll")                                                             \
    for (int i = 0; i < 8; i++) {                                                 \
        int r = (ROWBASE) + i;                                                    \
        if (r < N) {                                                              \
            float o[8];                                                           \
            _Pragma("unroll")                                                     \
            for (int j = 0; j < 4; j++)                                           \
                asm("mov.b64 {%0,%1}, %2;" : "=f"(o[2*j]), "=f"(o[2*j+1]) : "l"(acc[i][j])); \
            float* hp = (H2) + (size_t)r * D + cb;                                \
            *reinterpret_cast<float4*>(hp)     = make_float4(o[0], o[1], o[2], o[3]); \
            *reinterpret_cast<float4*>(hp + 4) = make_float4(o[4], o[5], o[6], o[7]); \
        }                                                                         \
    }

// ---------------- GEMM: H = X @ W  (128-row tiles, A from global) ----------------
__global__ void __launch_bounds__(256, 2) k_gemm(const float* __restrict__ X,
                                                 const float* __restrict__ W,
                                                 float* __restrict__ H, int N) {
    const int tid  = threadIdx.x;
    const int ry   = tid >> 4;          // 0..15
    const int cx   = tid & 15;          // 0..15
    const int row0 = blockIdx.x * 128 + ry * 8;
    const int cb   = cx * 8;

    int ridx[8];
#pragma unroll
    for (int i = 0; i < 8; i++) {
        int r = row0 + i;
        ridx[i] = (r < N) ? r : (N - 1);    // clamp: safe address, masked on store
    }
    const float4* x4 = reinterpret_cast<const float4*>(X);

#define LOAD_A_G(i) __ldg(x4 + (size_t)ridx[i] * 32 + kc)
    GEMM_INNER(LOAD_A_G)
#undef LOAD_A_G

    GEMM_STORE(H, row0)
}

// ---------------- gather helper: A[d] row (lane's float4), self-term + edges ----------------
__device__ __forceinline__ float4 gather_row(const float4* __restrict__ H4,
                                             int node, int lane) {
    int beg = g_rowptr[node], end = g_rowptr[node + 1];
    float dv  = g_dinv[node];
    float dv2 = dv * dv;
    float4 h  = H4[(size_t)node * 32 + lane];
    float4 acc = make_float4(h.x * dv2, h.y * dv2, h.z * dv2, h.w * dv2);

    int j = beg;
    for (; j + 4 <= end; j += 4) {
        int2 m0 = __ldg(&g_epack[j]);
        int2 m1 = __ldg(&g_epack[j + 1]);
        int2 m2 = __ldg(&g_epack[j + 2]);
        int2 m3 = __ldg(&g_epack[j + 3]);
        float4 h0 = H4[(size_t)m0.x * 32 + lane];
        float4 h1 = H4[(size_t)m1.x * 32 + lane];
        float4 h2 = H4[(size_t)m2.x * 32 + lane];
        float4 h3 = H4[(size_t)m3.x * 32 + lane];
        float w0 = __int_as_float(m0.y), w1 = __int_as_float(m1.y);
        float w2 = __int_as_float(m2.y), w3 = __int_as_float(m3.y);
        acc.x = fmaf(h0.x, w0, acc.x); acc.y = fmaf(h0.y, w0, acc.y);
        acc.z = fmaf(h0.z, w0, acc.z); acc.w = fmaf(h0.w, w0, acc.w);
        acc.x = fmaf(h1.x, w1, acc.x); acc.y = fmaf(h1.y, w1, acc.y);
        acc.z = fmaf(h1.z, w1, acc.z); acc.w = fmaf(h1.w, w1, acc.w);
        acc.x = fmaf(h2.x, w2, acc.x); acc.y = fmaf(h2.y, w2, acc.y);
        acc.z = fmaf(h2.z, w2, acc.z); acc.w = fmaf(h2.w, w2, acc.w);
        acc.x = fmaf(h3.x, w3, acc.x); acc.y = fmaf(h3.y, w3, acc.y);
        acc.z = fmaf(h3.z, w3, acc.z); acc.w = fmaf(h3.w, w3, acc.w);
    }
    for (; j < end; j++) {
        int2 m = __ldg(&g_epack[j]);
        float4 hh = H4[(size_t)m.x * 32 + lane];
        float w = __int_as_float(m.y);
        acc.x = fmaf(hh.x, w, acc.x); acc.y = fmaf(hh.y, w, acc.y);
        acc.z = fmaf(hh.z, w, acc.z); acc.w = fmaf(hh.w, w, acc.w);
    }
    return acc;
}

// ---------------- fused: (gather1 + b1 + relu) -> smem (128x132) -> gemm2 -> H2 ----------------
__global__ void __launch_bounds__(256, 2) k_fused_ag(const float4* __restrict__ H4,
                                                     const float* __restrict__ bias,
                                                     const float* __restrict__ W,
                                                     float* __restrict__ H2, int N) {
    extern __shared__ float s_a[];       // 128 * 132 floats = 67584 B
    const int tid  = threadIdx.x;
    const int wid  = tid >> 5;
    const int lane = tid & 31;
    const int tile = blockIdx.x;

    float4 bb = reinterpret_cast<const float4*>(bias)[lane];

    // phase 1: 8 warps gather 16 nodes each into smem (bias+relu applied)
#pragma unroll 2
    for (int i = 0; i < 16; i++) {
        int lrow = wid * 16 + i;
        int node = tile * 128 + lrow;
        float4 v;
        if (node < N) {
            float4 acc = gather_row(H4, node, lane);
            v = make_float4(fmaxf(acc.x + bb.x, 0.0f), fmaxf(acc.y + bb.y, 0.0f),
                            fmaxf(acc.z + bb.z, 0.0f), fmaxf(acc.w + bb.w, 0.0f));
        } else {
            v = make_float4(0.0f, 0.0f, 0.0f, 0.0f);
        }
        *reinterpret_cast<float4*>(&s_a[lrow * 132 + lane * 4]) = v;
    }
    __syncthreads();

    // phase 2: GEMM from smem
    const int ry   = tid >> 4;
    const int cx   = tid & 15;
    const int lrow0 = ry * 8;
    const int cb   = cx * 8;

#define LOAD_A_S(i) (*reinterpret_cast<const float4*>(&s_a[(lrow0 + (i)) * 132 + kc * 4]))
    GEMM_INNER(LOAD_A_S)
#undef LOAD_A_S

    const int row0 = tile * 128 + lrow0;
    GEMM_STORE(H2, row0)
}

// ---------------- standalone gather (layer 2, no relu/bias) ----------------
__global__ void __launch_bounds__(256) k_gather2(const float4* __restrict__ H4,
                                                 float4* __restrict__ A4, int N) {
    int gw   = (blockIdx.x * blockDim.x + threadIdx.x) >> 5;
    int lane = threadIdx.x & 31;
    if (gw >= N) return;
    A4[(size_t)gw * 32 + lane] = gather_row(H4, gw, lane);
}

// ---------------- fused global-mean-pool (+b2,relu) + MLP head ----------------
__global__ void __launch_bounds__(128) k_pool_mlp(const float* __restrict__ AGG,
                                                  const float* __restrict__ b2,
                                                  int Nnodes,
                                                  const float* __restrict__ Wm1,
                                                  const float* __restrict__ bm1,
                                                  const float* __restrict__ Wm2,
                                                  const float* __restrict__ bm2,
                                                  const float* __restrict__ Wm3,
                                                  const float* __restrict__ bm3,
                                                  float* __restrict__ out) {
    const int g = blockIdx.x;
    const int tid = threadIdx.x;
    __shared__ int sb[2];
    __shared__ float gs[128];
    __shared__ float a1[500];
    __shared__ float a2[100];
    __shared__ float red[128];

    if (tid < 2) {
        int target = g + tid;
        int lo = 0, hi = Nnodes;
        while (lo < hi) {
            int mid = (lo + hi) >> 1;
            if (g_batch[mid] < target) lo = mid + 1; else hi = mid;
        }
        sb[tid] = lo;
    }
    __syncthreads();
    int beg = sb[0], end = sb[1];
    int cnt = end - beg;

    float bb = b2[tid];
    float sum = 0.0f;
#pragma unroll 4
    for (int n = beg; n < end; n++)
        sum += fmaxf(AGG[(size_t)n * D + tid] + bb, 0.0f);
    gs[tid] = sum / (float)max(cnt, 1);
    __syncthreads();

    for (int o = tid; o < 500; o += 128) {
        float acc = bm1[o];
#pragma unroll 4
        for (int j = 0; j < 128; j++)
            acc = fmaf(gs[j], Wm1[j * 500 + o], acc);
        a1[o] = fmaxf(acc, 0.0f);
    }
    __syncthreads();

    if (tid < 100) {
        float acc = bm2[tid];
        for (int j = 0; j < 500; j++)
            acc = fmaf(a1[j], Wm2[j * 100 + tid], acc);
        a2[tid] = fmaxf(acc, 0.0f);
    }
    __syncthreads();

    red[tid] = (tid < 100) ? a2[tid] * Wm3[tid] : 0.0f;
    __syncthreads();
    for (int s = 64; s > 0; s >>= 1) {
        if (tid < s) red[tid] += red[tid + s];
        __syncthreads();
    }
    if (tid == 0) out[g] = red[0] + bm3[0];
}

// ---------------- launch ----------------
extern "C" void kernel_launch(void* const* d_in, const int* in_sizes, int n_in,
                              void* d_out, int out_size) {
    const float* x     = (const float*)d_in[0];
    const void*  edges = d_in[1];
    const void*  batch = d_in[2];
    const float* W1  = (const float*)d_in[3];
    const float* b1  = (const float*)d_in[4];
    const float* W2  = (const float*)d_in[5];
    const float* b2  = (const float*)d_in[6];
    const float* Wm1 = (const float*)d_in[7];
    const float* bm1 = (const float*)d_in[8];
    const float* Wm2 = (const float*)d_in[9];
    const float* bm2 = (const float*)d_in[10];
    const float* Wm3 = (const float*)d_in[11];
    const float* bm3 = (const float*)d_in[12];
    float* out = (float*)d_out;

    const int N = in_sizes[0] / D;
    const int E = in_sizes[1] / 2;
    const int G = out_size;

    float *bufA = nullptr, *bufB = nullptr, *bufC = nullptr;
    cudaGetSymbolAddress((void**)&bufA, g_bufA);
    cudaGetSymbolAddress((void**)&bufB, g_bufB);
    cudaGetSymbolAddress((void**)&bufC, g_bufC);

    const int tB = 256;
    const int nodeB   = (N + tB - 1) / tB;
    const int edgeB   = (E + tB - 1) / tB;
    const int scanNb  = (N + 1023) / 1024;
    const int tiles   = (N + 127) / 128;
    const int warpB   = (N * 32 + tB - 1) / tB;    // 1 warp/node
    const int smemAG  = 128 * 132 * sizeof(float); // 67584 B

    // idempotent, non-stream API: safe every call, no static guards
    cudaFuncSetAttribute(k_fused_ag, cudaFuncAttributeMaxDynamicSharedMemorySize, smemAG);

    // 0: zero counts + detect dtype
    k_init<<<nodeB + 1, tB>>>((const unsigned int*)edges, N, nodeB);
    // 1: degree histogram + batch convert
    k_prep<<<edgeB, tB>>>(edges, batch, E, N);
    // 2: rowptr scan part 1
    k_scan_block<<<scanNb, 1024>>>(N);
    // 3: layer1 GEMM (independent of CSR) — ncu capture slot
    k_gemm<<<tiles, tB>>>(x, W1, bufA, N);
    // 4: rowptr scan part 2 (+dinv, cursor reset)
    k_scan_add<<<nodeB, tB>>>(N, E, scanNb);
    // 5: CSR fill
    k_fill<<<edgeB, tB>>>(edges, E);
    // 6: fused gather1+b1+relu -> gemm2
    k_fused_ag<<<tiles, tB, smemAG>>>((const float4*)bufA, b1, W2, bufB, N);
    // 7: layer2 aggregate
    k_gather2<<<warpB, tB>>>((const float4*)bufB, (float4*)bufC, N);
    // 8: pool + MLP head (applies b2 + relu)
    k_pool_mlp<<<G, 128>>>(bufC, b2, N, Wm1, bm1, Wm2, bm2, Wm3, bm3, out);
}

// round 13
// speedup vs baseline: 1.1751x; 1.0349x over previous
#include <cuda_runtime.h>

#define MAXN 100000
#define MAXE 1600000
#define D    128

// ---------------- scratch (static __device__ — no allocations) ----------------
__device__ float g_bufA[(size_t)MAXN * D];   // H (GEMM output)
__device__ float g_bufB[(size_t)MAXN * D];   // H2 (fused gather+gemm2 output)
__device__ float g_bufC[(size_t)MAXN * D];   // agg layer2 (pool input)
__device__ float g_dinv[MAXN];
__device__ int   g_counts[MAXN];
__device__ int   g_cursor[MAXN];
__device__ int   g_rowptr[MAXN + 1];
__device__ int   g_bsums[128];
__device__ int2  g_epack[MAXE];              // (src col, weight bits)
__device__ int   g_batch[MAXN];
__device__ int   g_is64;

// packed f32x2 FMA (Blackwell FFMA2 — only reachable via PTX fma.rn.f32x2)
#define FMA_F32X2(d, a, b) \
    asm("fma.rn.f32x2 %0, %1, %2, %0;" : "+l"(d) : "l"(a), "l"(b))

// ---------------- init: zero counts + dtype detect ----------------
// int64 indices < 100000: every odd 32-bit word is zero; impossible for random int32.
__global__ void k_init(const unsigned int* __restrict__ w, int N, int nodeB) {
    if (blockIdx.x < (unsigned)nodeB) {
        int i = blockIdx.x * 256 + threadIdx.x;
        if (i < N) g_counts[i] = 0;
    } else {
        __shared__ unsigned int s;
        if (threadIdx.x == 0) s = 0u;
        __syncthreads();
        unsigned int v = 0u;
        for (int i = threadIdx.x; i < 4096; i += 256) v |= w[2 * i + 1];
        atomicOr(&s, v);
        __syncthreads();
        if (threadIdx.x == 0) g_is64 = (s == 0u) ? 1 : 0;
    }
}

// ---------------- degree histogram + batch convert ----------------
__global__ void k_prep(const void* __restrict__ edges, const void* __restrict__ batch,
                       int E, int N) {
    int e = blockIdx.x * blockDim.x + threadIdx.x;
    if (e < E) {
        int d;
        if (g_is64) d = (int)((const long long*)edges)[e + E];
        else        d = ((const int*)edges)[e + E];
        atomicAdd(&g_counts[d], 1);
    }
    if (e < N) {
        if (g_is64) g_batch[e] = (int)((const long long*)batch)[e];
        else        g_batch[e] = ((const int*)batch)[e];
    }
}

// ---------------- exclusive scan over counts (also emits dinv) ----------------
__global__ void k_scan_block(int N) {
    __shared__ int s[1024];
    int tid = threadIdx.x;
    int i = blockIdx.x * 1024 + tid;
    int v = (i < N) ? g_counts[i] : 0;
    if (i < N) g_dinv[i] = rsqrtf((float)v + 1.0f);
    s[tid] = v;
    __syncthreads();
    for (int off = 1; off < 1024; off <<= 1) {
        int t = (tid >= off) ? s[tid - off] : 0;
        __syncthreads();
        s[tid] += t;
        __syncthreads();
    }
    if (i < N) g_rowptr[i] = s[tid] - v;          // exclusive
    if (tid == 1023) g_bsums[blockIdx.x] = s[1023];
}

// block-sums scanned redundantly per block (nb <= 128), then add + cursor reset
__global__ void k_scan_add(int N, int E, int nb) {
    __shared__ int s[128];
    __shared__ int ex[128];
    int tid = threadIdx.x;
    if (tid < 128) {
        int v = (tid < nb) ? g_bsums[tid] : 0;
        s[tid] = v;
        ex[tid] = v;
    }
    __syncthreads();
    for (int off = 1; off < 128; off <<= 1) {
        int t = 0;
        if (tid < 128 && tid >= off) t = s[tid - off];
        __syncthreads();
        if (tid < 128) s[tid] += t;
        __syncthreads();
    }
    if (tid < 128) ex[tid] = s[tid] - ex[tid];    // exclusive
    __syncthreads();
    int i = blockIdx.x * 256 + tid;
    if (i < N) { g_rowptr[i] += ex[i >> 10]; g_cursor[i] = 0; }
    if (i == 0) g_rowptr[N] = E;
}

// ---------------- CSR fill ----------------
__global__ void k_fill(const void* __restrict__ edges, int E) {
    int e = blockIdx.x * blockDim.x + threadIdx.x;
    if (e >= E) return;
    int s, d;
    if (g_is64) {
        const long long* p = (const long long*)edges;
        s = (int)p[e]; d = (int)p[e + E];
    } else {
        const int* p = (const int*)edges;
        s = p[e]; d = p[e + E];
    }
    int pos = atomicAdd(&g_cursor[d], 1);
    g_epack[g_rowptr[d] + pos] = make_int2(s, __float_as_int(g_dinv[s] * g_dinv[d]));
}

// ---------------- GEMM inner: 8 rows x 8 cols per thread, W from global (.nc) ----------------
#define GEMM_INNER(LOAD_A)                                                        \
    unsigned long long acc[8][4];                                                 \
    _Pragma("unroll")                                                             \
    for (int i = 0; i < 8; i++)                                                   \
        _Pragma("unroll")                                                         \
        for (int j = 0; j < 4; j++) acc[i][j] = 0ull;                             \
    const unsigned long long* wp = reinterpret_cast<const unsigned long long*>(W + cb); \
    _Pragma("unroll 2")                                                           \
    for (int kc = 0; kc < 32; kc++) {                                             \
        float4 a[8];                                                              \
        _Pragma("unroll")                                                         \
        for (int i = 0; i < 8; i++) a[i] = LOAD_A(i);                             \
        _Pragma("unroll")                                                         \
        for (int kk = 0; kk < 4; kk++) {                                          \
            unsigned long long w0, w1, w2, w3;                                    \
            asm("ld.global.nc.v2.u64 {%0,%1}, [%2];" : "=l"(w0), "=l"(w1) : "l"(wp));     \
            asm("ld.global.nc.v2.u64 {%0,%1}, [%2];" : "=l"(w2), "=l"(w3) : "l"(wp + 2)); \
            wp += 64;                                                             \
            _Pragma("unroll")                                                     \
            for (int i = 0; i < 8; i++) {                                         \
                float v = (kk == 0) ? a[i].x : (kk == 1) ? a[i].y                 \
                        : (kk == 2) ? a[i].z : a[i].w;                            \
                unsigned long long p;                                             \
                asm("mov.b64 %0, {%1,%1};" : "=l"(p) : "f"(v));                   \
                FMA_F32X2(acc[i][0], p, w0); FMA_F32X2(acc[i][1], p, w1);         \
                FMA_F32X2(acc[i][2], p, w2); FMA_F32X2(acc[i][3], p, w3);         \
            }                                                                     \
        }                                                                         \
    }

#define GEMM_STORE(H2, ROWBASE)                                                   \
    _Pragma("unroll")                                                             \
    for (int i = 0; i < 8; i++) {                                                 \
        int r = (ROWBASE) + i;                                                    \
        if (r < N) {                                                              \
            float o[8];                                                           \
            _Pragma("unroll")                                                     \
            for (int j = 0; j < 4; j++)                                           \
                asm("mov.b64 {%0,%1}, %2;" : "=f"(o[2*j]), "=f"(o[2*j+1]) : "l"(acc[i][j])); \
            float* hp = (H2) + (size_t)r * D + cb;                                \
            *reinterpret_cast<float4*>(hp)     = make_float4(o[0], o[1], o[2], o[3]); \
            *reinterpret_cast<float4*>(hp + 4) = make_float4(o[4], o[5], o[6], o[7]); \
        }                                                                         \
    }

// ---------------- GEMM: H = X @ W  (128-row tiles, A from global) ----------------
__global__ void __launch_bounds__(256, 2) k_gemm(const float* __restrict__ X,
                                                 const float* __restrict__ W,
                                                 float* __restrict__ H, int N) {
    const int tid  = threadIdx.x;
    const int ry   = tid >> 4;          // 0..15
    const int cx   = tid & 15;          // 0..15
    const int row0 = blockIdx.x * 128 + ry * 8;
    const int cb   = cx * 8;

    int ridx[8];
#pragma unroll
    for (int i = 0; i < 8; i++) {
        int r = row0 + i;
        ridx[i] = (r < N) ? r : (N - 1);    // clamp: safe address, masked on store
    }
    const float4* x4 = reinterpret_cast<const float4*>(X);

#define LOAD_A_G(i) __ldg(x4 + (size_t)ridx[i] * 32 + kc)
    GEMM_INNER(LOAD_A_G)
#undef LOAD_A_G

    GEMM_STORE(H, row0)
}

// ---------------- gather helper: A[d] row (lane's float4), self-term + edges ----------------
__device__ __forceinline__ float4 gather_row(const float4* __restrict__ H4,
                                             int node, int lane) {
    int beg = g_rowptr[node], end = g_rowptr[node + 1];
    float dv  = g_dinv[node];
    float dv2 = dv * dv;
    float4 h  = H4[(size_t)node * 32 + lane];
    float4 acc = make_float4(h.x * dv2, h.y * dv2, h.z * dv2, h.w * dv2);

    int j = beg;
    for (; j + 4 <= end; j += 4) {
        int2 m0 = __ldg(&g_epack[j]);
        int2 m1 = __ldg(&g_epack[j + 1]);
        int2 m2 = __ldg(&g_epack[j + 2]);
        int2 m3 = __ldg(&g_epack[j + 3]);
        float4 h0 = H4[(size_t)m0.x * 32 + lane];
        float4 h1 = H4[(size_t)m1.x * 32 + lane];
        float4 h2 = H4[(size_t)m2.x * 32 + lane];
        float4 h3 = H4[(size_t)m3.x * 32 + lane];
        float w0 = __int_as_float(m0.y), w1 = __int_as_float(m1.y);
        float w2 = __int_as_float(m2.y), w3 = __int_as_float(m3.y);
        acc.x = fmaf(h0.x, w0, acc.x); acc.y = fmaf(h0.y, w0, acc.y);
        acc.z = fmaf(h0.z, w0, acc.z); acc.w = fmaf(h0.w, w0, acc.w);
        acc.x = fmaf(h1.x, w1, acc.x); acc.y = fmaf(h1.y, w1, acc.y);
        acc.z = fmaf(h1.z, w1, acc.z); acc.w = fmaf(h1.w, w1, acc.w);
        acc.x = fmaf(h2.x, w2, acc.x); acc.y = fmaf(h2.y, w2, acc.y);
        acc.z = fmaf(h2.z, w2, acc.z); acc.w = fmaf(h2.w, w2, acc.w);
        acc.x = fmaf(h3.x, w3, acc.x); acc.y = fmaf(h3.y, w3, acc.y);
        acc.z = fmaf(h3.z, w3, acc.z); acc.w = fmaf(h3.w, w3, acc.w);
    }
    for (; j < end; j++) {
        int2 m = __ldg(&g_epack[j]);
        float4 hh = H4[(size_t)m.x * 32 + lane];
        float w = __int_as_float(m.y);
        acc.x = fmaf(hh.x, w, acc.x); acc.y = fmaf(hh.y, w, acc.y);
        acc.z = fmaf(hh.z, w, acc.z); acc.w = fmaf(hh.w, w, acc.w);
    }
    return acc;
}

// ---------------- fused: (gather1 + b1 + relu) -> smem (128x132) -> gemm2 -> H2 ----------------
__global__ void __launch_bounds__(256, 2) k_fused_ag(const float4* __restrict__ H4,
                                                     const float* __restrict__ bias,
                                                     const float* __restrict__ W,
                                                     float* __restrict__ H2, int N) {
    extern __shared__ float s_a[];       // 128 * 132 floats = 67584 B
    const int tid  = threadIdx.x;
    const int wid  = tid >> 5;
    const int lane = tid & 31;
    const int tile = blockIdx.x;

    float4 bb = reinterpret_cast<const float4*>(bias)[lane];

    // phase 1: 8 warps gather 16 nodes each into smem (bias+relu applied)
#pragma unroll 2
    for (int i = 0; i < 16; i++) {
        int lrow = wid * 16 + i;
        int node = tile * 128 + lrow;
        float4 v;
        if (node < N) {
            float4 acc = gather_row(H4, node, lane);
            v = make_float4(fmaxf(acc.x + bb.x, 0.0f), fmaxf(acc.y + bb.y, 0.0f),
                            fmaxf(acc.z + bb.z, 0.0f), fmaxf(acc.w + bb.w, 0.0f));
        } else {
            v = make_float4(0.0f, 0.0f, 0.0f, 0.0f);
        }
        *reinterpret_cast<float4*>(&s_a[lrow * 132 + lane * 4]) = v;
    }
    __syncthreads();

    // phase 2: GEMM from smem
    const int ry   = tid >> 4;
    const int cx   = tid & 15;
    const int lrow0 = ry * 8;
    const int cb   = cx * 8;

#define LOAD_A_S(i) (*reinterpret_cast<const float4*>(&s_a[(lrow0 + (i)) * 132 + kc * 4]))
    GEMM_INNER(LOAD_A_S)
#undef LOAD_A_S

    const int row0 = tile * 128 + lrow0;
    GEMM_STORE(H2, row0)
}

// ---------------- standalone gather (layer 2, no relu/bias) ----------------
__global__ void __launch_bounds__(256) k_gather2(const float4* __restrict__ H4,
                                                 float4* __restrict__ A4, int N) {
    int gw   = (blockIdx.x * blockDim.x + threadIdx.x) >> 5;
    int lane = threadIdx.x & 31;
    if (gw >= N) return;
    A4[(size_t)gw * 32 + lane] = gather_row(H4, gw, lane);
}

// ---------------- fused global-mean-pool (+b2,relu) + MLP head ----------------
__global__ void __launch_bounds__(128) k_pool_mlp(const float* __restrict__ AGG,
                                                  const float* __restrict__ b2,
                                                  int Nnodes,
                                                  const float* __restrict__ Wm1,
                                                  const float* __restrict__ bm1,
                                                  const float* __restrict__ Wm2,
                                                  const float* __restrict__ bm2,
                                                  const float* __restrict__ Wm3,
                                                  const float* __restrict__ bm3,
                                                  float* __restrict__ out) {
    const int g = blockIdx.x;
    const int tid = threadIdx.x;
    __shared__ int sb[2];
    __shared__ float gs[128];
    __shared__ float a1[500];
    __shared__ float a2[100];
    __shared__ float red[128];

    if (tid < 2) {
        int target = g + tid;
        int lo = 0, hi = Nnodes;
        while (lo < hi) {
            int mid = (lo + hi) >> 1;
            if (g_batch[mid] < target) lo = mid + 1; else hi = mid;
        }
        sb[tid] = lo;
    }
    __syncthreads();
    int beg = sb[0], end = sb[1];
    int cnt = end - beg;

    float bb = b2[tid];
    float sum = 0.0f;
#pragma unroll 4
    for (int n = beg; n < end; n++)
        sum += fmaxf(AGG[(size_t)n * D + tid] + bb, 0.0f);
    gs[tid] = sum / (float)max(cnt, 1);
    __syncthreads();

    for (int o = tid; o < 500; o += 128) {
        float acc = bm1[o];
#pragma unroll 4
        for (int j = 0; j < 128; j++)
            acc = fmaf(gs[j], Wm1[j * 500 + o], acc);
        a1[o] = fmaxf(acc, 0.0f);
    }
    __syncthreads();

    if (tid < 100) {
        float acc = bm2[tid];
        for (int j = 0; j < 500; j++)
            acc = fmaf(a1[j], Wm2[j * 100 + tid], acc);
        a2[tid] = fmaxf(acc, 0.0f);
    }
    __syncthreads();

    red[tid] = (tid < 100) ? a2[tid] * Wm3[tid] : 0.0f;
    __syncthreads();
    for (int s = 64; s > 0; s >>= 1) {
        if (tid < s) red[tid] += red[tid + s];
        __syncthreads();
    }
    if (tid == 0) out[g] = red[0] + bm3[0];
}

// ---------------- launch ----------------
extern "C" void kernel_launch(void* const* d_in, const int* in_sizes, int n_in,
                              void* d_out, int out_size) {
    const float* x     = (const float*)d_in[0];
    const void*  edges = d_in[1];
    const void*  batch = d_in[2];
    const float* W1  = (const float*)d_in[3];
    const float* b1  = (const float*)d_in[4];
    const float* W2  = (const float*)d_in[5];
    const float* b2  = (const float*)d_in[6];
    const float* Wm1 = (const float*)d_in[7];
    const float* bm1 = (const float*)d_in[8];
    const float* Wm2 = (const float*)d_in[9];
    const float* bm2 = (const float*)d_in[10];
    const float* Wm3 = (const float*)d_in[11];
    const float* bm3 = (const float*)d_in[12];
    float* out = (float*)d_out;

    const int N = in_sizes[0] / D;
    const int E = in_sizes[1] / 2;
    const int G = out_size;

    float *bufA = nullptr, *bufB = nullptr, *bufC = nullptr;
    cudaGetSymbolAddress((void**)&bufA, g_bufA);
    cudaGetSymbolAddress((void**)&bufB, g_bufB);
    cudaGetSymbolAddress((void**)&bufC, g_bufC);

    const int tB = 256;
    const int nodeB   = (N + tB - 1) / tB;
    const int edgeB   = (E + tB - 1) / tB;
    const int scanNb  = (N + 1023) / 1024;
    const int tiles   = (N + 127) / 128;
    const int warpB   = (N * 32 + tB - 1) / tB;    // 1 warp/node
    const int smemAG  = 128 * 132 * sizeof(float); // 67584 B

    // idempotent, non-stream API: safe every call, no static guards
    cudaFuncSetAttribute(k_fused_ag, cudaFuncAttributeMaxDynamicSharedMemorySize, smemAG);

    // Fork infra: side stream + events, created per call, never destroyed
    // (kernel_launch runs only for correctness + capture — a handful of tiny
    // host-side objects total; no device-memory allocation involved).
    cudaStream_t s2;
    cudaStreamCreateWithFlags(&s2, cudaStreamNonBlocking);
    cudaEvent_t evFork, evJoin;
    cudaEventCreateWithFlags(&evFork, cudaEventDisableTiming);
    cudaEventCreateWithFlags(&evJoin, cudaEventDisableTiming);

    // Fork point at entry of the capture stream: gemm1 depends on nothing.
    cudaEventRecord(evFork, 0);
    cudaStreamWaitEvent(s2, evFork, 0);

    // Branch B (main stream): CSR build chain
    k_init<<<nodeB + 1, tB>>>((const unsigned int*)edges, N, nodeB);        // 0
    k_prep<<<edgeB, tB>>>(edges, batch, E, N);                              // 1
    k_scan_block<<<scanNb, 1024>>>(N);                                      // 2
    // Branch A (side stream): layer1 GEMM — parallel branch in the graph
    k_gemm<<<tiles, tB, 0, s2>>>(x, W1, bufA, N);                           // 3 (ncu slot)
    cudaEventRecord(evJoin, s2);
    // Branch B continues
    k_scan_add<<<nodeB, tB>>>(N, E, scanNb);                                // 4
    k_fill<<<edgeB, tB>>>(edges, E);                                        // 5

    // Join: fused gather1+gemm2 needs both bufA and the CSR
    cudaStreamWaitEvent(0, evJoin, 0);
    k_fused_ag<<<tiles, tB, smemAG>>>((const float4*)bufA, b1, W2, bufB, N);
    k_gather2<<<warpB, tB>>>((const float4*)bufB, (float4*)bufC, N);
    k_pool_mlp<<<G, 128>>>(bufC, b2, N, Wm1, bm1, Wm2, bm2, Wm3, bm3, out);
}

// round 15
// speedup vs baseline: 1.2444x; 1.0590x over previous
#include <cuda_runtime.h>

#define MAXN 100000
#define MAXE 1600000
#define D    128
#define APAD 36          // 32 floats per chunk row + 4 pad

// ---------------- scratch (static __device__ — no allocations) ----------------
__device__ float g_bufA[(size_t)MAXN * D];   // H (GEMM output)
__device__ float g_bufB[(size_t)MAXN * D];   // H2 (fused gather+gemm2 output)
__device__ float g_bufC[(size_t)MAXN * D];   // agg layer2 (pool input)
__device__ float g_dinv[MAXN];
__device__ int   g_counts[MAXN];
__device__ int   g_cursor[MAXN];
__device__ int   g_rowptr[MAXN + 1];
__device__ int   g_bsums[128];
__device__ int2  g_epack[MAXE];              // (src col, weight bits)
__device__ int   g_batch[MAXN];
__device__ int   g_is64;

// packed f32x2 FMA (Blackwell FFMA2 — only reachable via PTX fma.rn.f32x2)
#define FMA_F32X2(d, a, b) \
    asm("fma.rn.f32x2 %0, %1, %2, %0;" : "+l"(d) : "l"(a), "l"(b))

// ---------------- init: zero counts + dtype detect ----------------
// int64 indices < 100000: every odd 32-bit word is zero; impossible for random int32.
__global__ void k_init(const unsigned int* __restrict__ w, int N, int nodeB) {
    if (blockIdx.x < (unsigned)nodeB) {
        int i = blockIdx.x * 256 + threadIdx.x;
        if (i < N) g_counts[i] = 0;
    } else {
        __shared__ unsigned int s;
        if (threadIdx.x == 0) s = 0u;
        __syncthreads();
        unsigned int v = 0u;
        for (int i = threadIdx.x; i < 4096; i += 256) v |= w[2 * i + 1];
        atomicOr(&s, v);
        __syncthreads();
        if (threadIdx.x == 0) g_is64 = (s == 0u) ? 1 : 0;
    }
}

// ---------------- degree histogram + batch convert ----------------
__global__ void k_prep(const void* __restrict__ edges, const void* __restrict__ batch,
                       int E, int N) {
    int e = blockIdx.x * blockDim.x + threadIdx.x;
    if (e < E) {
        int d;
        if (g_is64) d = (int)((const long long*)edges)[e + E];
        else        d = ((const int*)edges)[e + E];
        atomicAdd(&g_counts[d], 1);
    }
    if (e < N) {
        if (g_is64) g_batch[e] = (int)((const long long*)batch)[e];
        else        g_batch[e] = ((const int*)batch)[e];
    }
}

// ---------------- exclusive scan over counts (also emits dinv) ----------------
__global__ void k_scan_block(int N) {
    __shared__ int s[1024];
    int tid = threadIdx.x;
    int i = blockIdx.x * 1024 + tid;
    int v = (i < N) ? g_counts[i] : 0;
    if (i < N) g_dinv[i] = rsqrtf((float)v + 1.0f);
    s[tid] = v;
    __syncthreads();
    for (int off = 1; off < 1024; off <<= 1) {
        int t = (tid >= off) ? s[tid - off] : 0;
        __syncthreads();
        s[tid] += t;
        __syncthreads();
    }
    if (i < N) g_rowptr[i] = s[tid] - v;          // exclusive
    if (tid == 1023) g_bsums[blockIdx.x] = s[1023];
}

// block-sums scanned redundantly per block (nb <= 128), then add + cursor reset
__global__ void k_scan_add(int N, int E, int nb) {
    __shared__ int s[128];
    __shared__ int ex[128];
    int tid = threadIdx.x;
    if (tid < 128) {
        int v = (tid < nb) ? g_bsums[tid] : 0;
        s[tid] = v;
        ex[tid] = v;
    }
    __syncthreads();
    for (int off = 1; off < 128; off <<= 1) {
        int t = 0;
        if (tid < 128 && tid >= off) t = s[tid - off];
        __syncthreads();
        if (tid < 128) s[tid] += t;
        __syncthreads();
    }
    if (tid < 128) ex[tid] = s[tid] - ex[tid];    // exclusive
    __syncthreads();
    int i = blockIdx.x * 256 + tid;
    if (i < N) { g_rowptr[i] += ex[i >> 10]; g_cursor[i] = 0; }
    if (i == 0) g_rowptr[N] = E;
}

// ---------------- CSR fill ----------------
__global__ void k_fill(const void* __restrict__ edges, int E) {
    int e = blockIdx.x * blockDim.x + threadIdx.x;
    if (e >= E) return;
    int s, d;
    if (g_is64) {
        const long long* p = (const long long*)edges;
        s = (int)p[e]; d = (int)p[e + E];
    } else {
        const int* p = (const int*)edges;
        s = p[e]; d = p[e + E];
    }
    int pos = atomicAdd(&g_cursor[d], 1);
    g_epack[g_rowptr[d] + pos] = make_int2(s, __float_as_int(g_dinv[s] * g_dinv[d]));
}

// ---------------- GEMM inner: 8 rows x 8 cols per thread, W from global (.nc) ----------------
// One "kc" = 4 consecutive k values. LOAD_A(i) yields float4 for row i at current kc.
#define GEMM_KC_BODY(LOAD_A)                                                      \
    {                                                                             \
        float4 a[8];                                                              \
        _Pragma("unroll")                                                         \
        for (int i = 0; i < 8; i++) a[i] = LOAD_A(i);                             \
        _Pragma("unroll")                                                         \
        for (int kk = 0; kk < 4; kk++) {                                          \
            unsigned long long w0, w1, w2, w3;                                    \
            asm("ld.global.nc.v2.u64 {%0,%1}, [%2];" : "=l"(w0), "=l"(w1) : "l"(wp));     \
            asm("ld.global.nc.v2.u64 {%0,%1}, [%2];" : "=l"(w2), "=l"(w3) : "l"(wp + 2)); \
            wp += 64;                                                             \
            _Pragma("unroll")                                                     \
            for (int i = 0; i < 8; i++) {                                         \
                float v = (kk == 0) ? a[i].x : (kk == 1) ? a[i].y                 \
                        : (kk == 2) ? a[i].z : a[i].w;                            \
                unsigned long long p;                                             \
                asm("mov.b64 %0, {%1,%1};" : "=l"(p) : "f"(v));                   \
                FMA_F32X2(acc[i][0], p, w0); FMA_F32X2(acc[i][1], p, w1);         \
                FMA_F32X2(acc[i][2], p, w2); FMA_F32X2(acc[i][3], p, w3);         \
            }                                                                     \
        }                                                                         \
    }

#define GEMM_STORE(H2, ROWBASE)                                                   \
    _Pragma("unroll")                                                             \
    for (int i = 0; i < 8; i++) {                                                 \
        int r = (ROWBASE) + i;                                                    \
        if (r < N) {                                                              \
            float o[8];                                                           \
            _Pragma("unroll")                                                     \
            for (int j = 0; j < 4; j++)                                           \
                asm("mov.b64 {%0,%1}, %2;" : "=f"(o[2*j]), "=f"(o[2*j+1]) : "l"(acc[i][j])); \
            float* hp = (H2) + (size_t)r * D + cb;                                \
            *reinterpret_cast<float4*>(hp)     = make_float4(o[0], o[1], o[2], o[3]); \
            *reinterpret_cast<float4*>(hp + 4) = make_float4(o[4], o[5], o[6], o[7]); \
        }                                                                         \
    }

// ---------------- GEMM: H = X @ W  (128-row tiles, X via cp.async double buffer) ----------------
// chunk = 32 k-floats (128 B/row); 4 chunks cover K=128
__global__ void __launch_bounds__(256, 2) k_gemm(const float* __restrict__ X,
                                                 const float* __restrict__ W,
                                                 float* __restrict__ H, int N) {
    __shared__ float s_a[2][128 * APAD];     // 2 x 18.4 KB
    const int tid  = threadIdx.x;
    const int ry   = tid >> 4;               // 0..15
    const int cx   = tid & 15;               // 0..15
    const int tileRow0 = blockIdx.x * 128;
    const int row0 = tileRow0 + ry * 8;
    const int cb   = cx * 8;

    // per-thread copy mapping: 4 x 16B ops per chunk (1024 ops = 128 rows x 8 segs)
    unsigned sbase[2];
    sbase[0] = (unsigned)__cvta_generic_to_shared(&s_a[0][0]);
    sbase[1] = (unsigned)__cvta_generic_to_shared(&s_a[1][0]);

#define COPY_CHUNK(BUF, C)                                                        \
    {                                                                             \
        _Pragma("unroll")                                                         \
        for (int t = 0; t < 4; t++) {                                             \
            int idx = t * 256 + tid;                                              \
            int crow = idx >> 3;                                                  \
            int seg  = idx & 7;                                                   \
            int grow = tileRow0 + crow;                                           \
            if (grow >= N) grow = N - 1;                                          \
            const char* src = (const char*)(X + (size_t)grow * D) + (C) * 128 + seg * 16; \
            unsigned dst = sbase[BUF] + (unsigned)(crow * APAD * 4 + seg * 16);   \
            asm volatile("cp.async.cg.shared.global [%0], [%1], 16;" :: "r"(dst), "l"(src)); \
        }                                                                         \
        asm volatile("cp.async.commit_group;");                                   \
    }

    unsigned long long acc[8][4];
#pragma unroll
    for (int i = 0; i < 8; i++)
#pragma unroll
        for (int j = 0; j < 4; j++) acc[i][j] = 0ull;

    const unsigned long long* wp = reinterpret_cast<const unsigned long long*>(W + cb);

    COPY_CHUNK(0, 0)

    for (int c = 0; c < 4; c++) {
        if (c < 3) {
            COPY_CHUNK((c + 1) & 1, c + 1)
            asm volatile("cp.async.wait_group 1;");
        } else {
            asm volatile("cp.async.wait_group 0;");
        }
        __syncthreads();
        const float* ab = &s_a[c & 1][0];
#pragma unroll
        for (int kc8 = 0; kc8 < 8; kc8++) {
#define LOAD_A_P(i) (*reinterpret_cast<const float4*>(ab + (ry * 8 + (i)) * APAD + kc8 * 4))
            GEMM_KC_BODY(LOAD_A_P)
#undef LOAD_A_P
        }
        __syncthreads();   // all reads done before next copy overwrites the other buffer
    }
#undef COPY_CHUNK

    GEMM_STORE(H, row0)
}

// ---------------- gather helper: A[d] row (lane's float4), self-term + edges ----------------
__device__ __forceinline__ float4 gather_row(const float4* __restrict__ H4,
                                             int node, int lane) {
    int beg = g_rowptr[node], end = g_rowptr[node + 1];
    float dv  = g_dinv[node];
    float dv2 = dv * dv;
    float4 h  = H4[(size_t)node * 32 + lane];
    float4 acc = make_float4(h.x * dv2, h.y * dv2, h.z * dv2, h.w * dv2);

    int j = beg;
    for (; j + 4 <= end; j += 4) {
        int2 m0 = __ldg(&g_epack[j]);
        int2 m1 = __ldg(&g_epack[j + 1]);
        int2 m2 = __ldg(&g_epack[j + 2]);
        int2 m3 = __ldg(&g_epack[j + 3]);
        float4 h0 = H4[(size_t)m0.x * 32 + lane];
        float4 h1 = H4[(size_t)m1.x * 32 + lane];
        float4 h2 = H4[(size_t)m2.x * 32 + lane];
        float4 h3 = H4[(size_t)m3.x * 32 + lane];
        float w0 = __int_as_float(m0.y), w1 = __int_as_float(m1.y);
        float w2 = __int_as_float(m2.y), w3 = __int_as_float(m3.y);
        acc.x = fmaf(h0.x, w0, acc.x); acc.y = fmaf(h0.y, w0, acc.y);
        acc.z = fmaf(h0.z, w0, acc.z); acc.w = fmaf(h0.w, w0, acc.w);
        acc.x = fmaf(h1.x, w1, acc.x); acc.y = fmaf(h1.y, w1, acc.y);
        acc.z = fmaf(h1.z, w1, acc.z); acc.w = fmaf(h1.w, w1, acc.w);
        acc.x = fmaf(h2.x, w2, acc.x); acc.y = fmaf(h2.y, w2, acc.y);
        acc.z = fmaf(h2.z, w2, acc.z); acc.w = fmaf(h2.w, w2, acc.w);
        acc.x = fmaf(h3.x, w3, acc.x); acc.y = fmaf(h3.y, w3, acc.y);
        acc.z = fmaf(h3.z, w3, acc.z); acc.w = fmaf(h3.w, w3, acc.w);
    }
    for (; j < end; j++) {
        int2 m = __ldg(&g_epack[j]);
        float4 hh = H4[(size_t)m.x * 32 + lane];
        float w = __int_as_float(m.y);
        acc.x = fmaf(hh.x, w, acc.x); acc.y = fmaf(hh.y, w, acc.y);
        acc.z = fmaf(hh.z, w, acc.z); acc.w = fmaf(hh.w, w, acc.w);
    }
    return acc;
}

// ---------------- fused: (gather1 + b1 + relu) -> smem (128x132) -> gemm2 -> H2 ----------------
__global__ void __launch_bounds__(256, 2) k_fused_ag(const float4* __restrict__ H4,
                                                     const float* __restrict__ bias,
                                                     const float* __restrict__ W,
                                                     float* __restrict__ H2, int N) {
    extern __shared__ float s_a[];       // 128 * 132 floats = 67584 B
    const int tid  = threadIdx.x;
    const int wid  = tid >> 5;
    const int lane = tid & 31;
    const int tile = blockIdx.x;

    float4 bb = reinterpret_cast<const float4*>(bias)[lane];

    // phase 1: 8 warps gather 16 nodes each into smem (bias+relu applied)
#pragma unroll 2
    for (int i = 0; i < 16; i++) {
        int lrow = wid * 16 + i;
        int node = tile * 128 + lrow;
        float4 v;
        if (node < N) {
            float4 acc4 = gather_row(H4, node, lane);
            v = make_float4(fmaxf(acc4.x + bb.x, 0.0f), fmaxf(acc4.y + bb.y, 0.0f),
                            fmaxf(acc4.z + bb.z, 0.0f), fmaxf(acc4.w + bb.w, 0.0f));
        } else {
            v = make_float4(0.0f, 0.0f, 0.0f, 0.0f);
        }
        *reinterpret_cast<float4*>(&s_a[lrow * 132 + lane * 4]) = v;
    }
    __syncthreads();

    // phase 2: GEMM from smem
    const int ry    = tid >> 4;
    const int cx    = tid & 15;
    const int lrow0 = ry * 8;
    const int cb    = cx * 8;

    unsigned long long acc[8][4];
#pragma unroll
    for (int i = 0; i < 8; i++)
#pragma unroll
        for (int j = 0; j < 4; j++) acc[i][j] = 0ull;

    const unsigned long long* wp = reinterpret_cast<const unsigned long long*>(W + cb);

#pragma unroll 2
    for (int kc = 0; kc < 32; kc++) {
#define LOAD_A_S(i) (*reinterpret_cast<const float4*>(&s_a[(lrow0 + (i)) * 132 + kc * 4]))
        GEMM_KC_BODY(LOAD_A_S)
#undef LOAD_A_S
    }

    const int row0 = tile * 128 + lrow0;
    GEMM_STORE(H2, row0)
}

// ---------------- standalone gather (layer 2, no relu/bias) ----------------
__global__ void __launch_bounds__(256) k_gather2(const float4* __restrict__ H4,
                                                 float4* __restrict__ A4, int N) {
    int gw   = (blockIdx.x * blockDim.x + threadIdx.x) >> 5;
    int lane = threadIdx.x & 31;
    if (gw >= N) return;
    A4[(size_t)gw * 32 + lane] = gather_row(H4, gw, lane);
}

// ---------------- fused global-mean-pool (+b2,relu) + MLP head ----------------
__global__ void __launch_bounds__(128) k_pool_mlp(const float* __restrict__ AGG,
                                                  const float* __restrict__ b2,
                                                  int Nnodes,
                                                  const float* __restrict__ Wm1,
                                                  const float* __restrict__ bm1,
                                                  const float* __restrict__ Wm2,
                                                  const float* __restrict__ bm2,
                                                  const float* __restrict__ Wm3,
                                                  const float* __restrict__ bm3,
                                                  float* __restrict__ out) {
    const int g = blockIdx.x;
    const int tid = threadIdx.x;
    __shared__ int sb[2];
    __shared__ float gs[128];
    __shared__ float a1[500];
    __shared__ float a2[100];
    __shared__ float red[128];

    if (tid < 2) {
        int target = g + tid;
        int lo = 0, hi = Nnodes;
        while (lo < hi) {
            int mid = (lo + hi) >> 1;
            if (g_batch[mid] < target) lo = mid + 1; else hi = mid;
        }
        sb[tid] = lo;
    }
    __syncthreads();
    int beg = sb[0], end = sb[1];
    int cnt = end - beg;

    float bb = b2[tid];
    float sum = 0.0f;
#pragma unroll 4
    for (int n = beg; n < end; n++)
        sum += fmaxf(AGG[(size_t)n * D + tid] + bb, 0.0f);
    gs[tid] = sum / (float)max(cnt, 1);
    __syncthreads();

    for (int o = tid; o < 500; o += 128) {
        float acc = bm1[o];
#pragma unroll 4
        for (int j = 0; j < 128; j++)
            acc = fmaf(gs[j], Wm1[j * 500 + o], acc);
        a1[o] = fmaxf(acc, 0.0f);
    }
    __syncthreads();

    if (tid < 100) {
        float acc = bm2[tid];
        for (int j = 0; j < 500; j++)
            acc = fmaf(a1[j], Wm2[j * 100 + tid], acc);
        a2[tid] = fmaxf(acc, 0.0f);
    }
    __syncthreads();

    red[tid] = (tid < 100) ? a2[tid] * Wm3[tid] : 0.0f;
    __syncthreads();
    for (int s = 64; s > 0; s >>= 1) {
        if (tid < s) red[tid] += red[tid + s];
        __syncthreads();
    }
    if (tid == 0) out[g] = red[0] + bm3[0];
}

// ---------------- launch ----------------
extern "C" void kernel_launch(void* const* d_in, const int* in_sizes, int n_in,
                              void* d_out, int out_size) {
    const float* x     = (const float*)d_in[0];
    const void*  edges = d_in[1];
    const void*  batch = d_in[2];
    const float* W1  = (const float*)d_in[3];
    const float* b1  = (const float*)d_in[4];
    const float* W2  = (const float*)d_in[5];
    const float* b2  = (const float*)d_in[6];
    const float* Wm1 = (const float*)d_in[7];
    const float* bm1 = (const float*)d_in[8];
    const float* Wm2 = (const float*)d_in[9];
    const float* bm2 = (const float*)d_in[10];
    const float* Wm3 = (const float*)d_in[11];
    const float* bm3 = (const float*)d_in[12];
    float* out = (float*)d_out;

    const int N = in_sizes[0] / D;
    const int E = in_sizes[1] / 2;
    const int G = out_size;

    float *bufA = nullptr, *bufB = nullptr, *bufC = nullptr;
    cudaGetSymbolAddress((void**)&bufA, g_bufA);
    cudaGetSymbolAddress((void**)&bufB, g_bufB);
    cudaGetSymbolAddress((void**)&bufC, g_bufC);

    const int tB = 256;
    const int nodeB   = (N + tB - 1) / tB;
    const int edgeB   = (E + tB - 1) / tB;
    const int scanNb  = (N + 1023) / 1024;
    const int tiles   = (N + 127) / 128;
    const int warpB   = (N * 32 + tB - 1) / tB;    // 1 warp/node
    const int smemAG  = 128 * 132 * sizeof(float); // 67584 B

    // idempotent, non-stream API: safe every call, no static guards
    cudaFuncSetAttribute(k_fused_ag, cudaFuncAttributeMaxDynamicSharedMemorySize, smemAG);

    // Fork infra: side stream + events, created per call, never destroyed
    cudaStream_t s2;
    cudaStreamCreateWithFlags(&s2, cudaStreamNonBlocking);
    cudaEvent_t evFork, evJoin;
    cudaEventCreateWithFlags(&evFork, cudaEventDisableTiming);
    cudaEventCreateWithFlags(&evJoin, cudaEventDisableTiming);

    // Fork point at entry of the capture stream: gemm1 depends on nothing.
    cudaEventRecord(evFork, 0);
    cudaStreamWaitEvent(s2, evFork, 0);

    // Branch B (main stream): CSR build chain
    k_init<<<nodeB + 1, tB>>>((const unsigned int*)edges, N, nodeB);        // 0
    k_prep<<<edgeB, tB>>>(edges, batch, E, N);                              // 1
    k_scan_block<<<scanNb, 1024>>>(N);                                      // 2
    // Branch A (side stream): layer1 GEMM — parallel branch in the graph
    k_gemm<<<tiles, tB, 0, s2>>>(x, W1, bufA, N);                           // 3 (ncu slot)
    cudaEventRecord(evJoin, s2);
    // Branch B continues
    k_scan_add<<<nodeB, tB>>>(N, E, scanNb);                                // 4
    k_fill<<<edgeB, tB>>>(edges, E);                                        // 5

    // Join: fused gather1+gemm2 needs both bufA and the CSR
    cudaStreamWaitEvent(0, evJoin, 0);
    k_fused_ag<<<tiles, tB, smemAG>>>((const float4*)bufA, b1, W2, bufB, N);
    k_gather2<<<warpB, tB>>>((const float4*)bufB, (float4*)bufC, N);
    k_pool_mlp<<<G, 128>>>(bufC, b2, N, Wm1, bm1, Wm2, bm2, Wm3, bm3, out);
}

// round 16
// speedup vs baseline: 1.3090x; 1.0519x over previous
#include <cuda_runtime.h>
#include <cuda_bf16.h>

#define MAXN 100000
#define MAXE 1600000
#define D    128
#define APAD 36          // 32 floats per chunk row + 4 pad

// ---------------- scratch (static __device__ — no allocations) ----------------
__device__ __nv_bfloat162 g_hA[(size_t)MAXN * 64];   // H  (layer1 GEMM out, bf16)
__device__ __nv_bfloat162 g_hB[(size_t)MAXN * 64];   // H2 (layer2 GEMM out, bf16)
__device__ float g_bufC[(size_t)MAXN * D];           // agg2 (pool input, fp32)
__device__ float g_dinv[MAXN];
__device__ int   g_counts[MAXN];
__device__ int   g_cursor[MAXN];
__device__ int   g_rowptr[MAXN + 1];
__device__ int   g_bsums[128];
__device__ int2  g_epack[MAXE];              // (src col, weight bits)
__device__ int   g_batch[MAXN];
__device__ int   g_is64;

// packed f32x2 FMA (Blackwell FFMA2 — only reachable via PTX fma.rn.f32x2)
#define FMA_F32X2(d, a, b) \
    asm("fma.rn.f32x2 %0, %1, %2, %0;" : "+l"(d) : "l"(a), "l"(b))

// bf16 pack/unpack (storage-only compression; all math in fp32)
__device__ __forceinline__ unsigned pk2(float lo, float hi) {
    __nv_bfloat162 b = __float22bfloat162_rn(make_float2(lo, hi));
    return *reinterpret_cast<unsigned*>(&b);
}
__device__ __forceinline__ float4 up4(uint2 v) {
    float2 f0 = __bfloat1622float2(*reinterpret_cast<__nv_bfloat162*>(&v.x));
    float2 f1 = __bfloat1622float2(*reinterpret_cast<__nv_bfloat162*>(&v.y));
    return make_float4(f0.x, f0.y, f1.x, f1.y);
}

// ---------------- init: zero counts + dtype detect ----------------
// int64 indices < 100000: every odd 32-bit word is zero; impossible for random int32.
__global__ void k_init(const unsigned int* __restrict__ w, int N, int nodeB) {
    if (blockIdx.x < (unsigned)nodeB) {
        int i = blockIdx.x * 256 + threadIdx.x;
        if (i < N) g_counts[i] = 0;
    } else {
        __shared__ unsigned int s;
        if (threadIdx.x == 0) s = 0u;
        __syncthreads();
        unsigned int v = 0u;
        for (int i = threadIdx.x; i < 4096; i += 256) v |= w[2 * i + 1];
        atomicOr(&s, v);
        __syncthreads();
        if (threadIdx.x == 0) g_is64 = (s == 0u) ? 1 : 0;
    }
}

// ---------------- degree histogram + batch convert ----------------
__global__ void k_prep(const void* __restrict__ edges, const void* __restrict__ batch,
                       int E, int N) {
    int e = blockIdx.x * blockDim.x + threadIdx.x;
    if (e < E) {
        int d;
        if (g_is64) d = (int)((const long long*)edges)[e + E];
        else        d = ((const int*)edges)[e + E];
        atomicAdd(&g_counts[d], 1);
    }
    if (e < N) {
        if (g_is64) g_batch[e] = (int)((const long long*)batch)[e];
        else        g_batch[e] = ((const int*)batch)[e];
    }
}

// ---------------- exclusive scan over counts (also emits dinv) ----------------
__global__ void k_scan_block(int N) {
    __shared__ int s[1024];
    int tid = threadIdx.x;
    int i = blockIdx.x * 1024 + tid;
    int v = (i < N) ? g_counts[i] : 0;
    if (i < N) g_dinv[i] = rsqrtf((float)v + 1.0f);
    s[tid] = v;
    __syncthreads();
    for (int off = 1; off < 1024; off <<= 1) {
        int t = (tid >= off) ? s[tid - off] : 0;
        __syncthreads();
        s[tid] += t;
        __syncthreads();
    }
    if (i < N) g_rowptr[i] = s[tid] - v;          // exclusive
    if (tid == 1023) g_bsums[blockIdx.x] = s[1023];
}

// block-sums scanned redundantly per block (nb <= 128), then add + cursor reset
__global__ void k_scan_add(int N, int E, int nb) {
    __shared__ int s[128];
    __shared__ int ex[128];
    int tid = threadIdx.x;
    if (tid < 128) {
        int v = (tid < nb) ? g_bsums[tid] : 0;
        s[tid] = v;
        ex[tid] = v;
    }
    __syncthreads();
    for (int off = 1; off < 128; off <<= 1) {
        int t = 0;
        if (tid < 128 && tid >= off) t = s[tid - off];
        __syncthreads();
        if (tid < 128) s[tid] += t;
        __syncthreads();
    }
    if (tid < 128) ex[tid] = s[tid] - ex[tid];    // exclusive
    __syncthreads();
    int i = blockIdx.x * 256 + tid;
    if (i < N) { g_rowptr[i] += ex[i >> 10]; g_cursor[i] = 0; }
    if (i == 0) g_rowptr[N] = E;
}

// ---------------- CSR fill ----------------
__global__ void k_fill(const void* __restrict__ edges, int E) {
    int e = blockIdx.x * blockDim.x + threadIdx.x;
    if (e >= E) return;
    int s, d;
    if (g_is64) {
        const long long* p = (const long long*)edges;
        s = (int)p[e]; d = (int)p[e + E];
    } else {
        const int* p = (const int*)edges;
        s = p[e]; d = p[e + E];
    }
    int pos = atomicAdd(&g_cursor[d], 1);
    g_epack[g_rowptr[d] + pos] = make_int2(s, __float_as_int(g_dinv[s] * g_dinv[d]));
}

// ---------------- GEMM inner: 8 rows x 8 cols per thread, W from global (.nc) ----------------
// One "kc" = 4 consecutive k values. LOAD_A(i) yields float4 for row i at current kc.
#define GEMM_KC_BODY(LOAD_A)                                                      \
    {                                                                             \
        float4 a[8];                                                              \
        _Pragma("unroll")                                                         \
        for (int i = 0; i < 8; i++) a[i] = LOAD_A(i);                             \
        _Pragma("unroll")                                                         \
        for (int kk = 0; kk < 4; kk++) {                                          \
            unsigned long long w0, w1, w2, w3;                                    \
            asm("ld.global.nc.v2.u64 {%0,%1}, [%2];" : "=l"(w0), "=l"(w1) : "l"(wp));     \
            asm("ld.global.nc.v2.u64 {%0,%1}, [%2];" : "=l"(w2), "=l"(w3) : "l"(wp + 2)); \
            wp += 64;                                                             \
            _Pragma("unroll")                                                     \
            for (int i = 0; i < 8; i++) {                                         \
                float v = (kk == 0) ? a[i].x : (kk == 1) ? a[i].y                 \
                        : (kk == 2) ? a[i].z : a[i].w;                            \
                unsigned long long p;                                             \
                asm("mov.b64 %0, {%1,%1};" : "=l"(p) : "f"(v));                   \
                FMA_F32X2(acc[i][0], p, w0); FMA_F32X2(acc[i][1], p, w1);         \
                FMA_F32X2(acc[i][2], p, w2); FMA_F32X2(acc[i][3], p, w3);         \
            }                                                                     \
        }                                                                         \
    }

// store 8 fp32 cols as 4 bf162 words (uint4) into bf16 H layout (64 bf162 per row)
#define GEMM_STORE_BF16(HB, ROWBASE)                                              \
    _Pragma("unroll")                                                             \
    for (int i = 0; i < 8; i++) {                                                 \
        int r = (ROWBASE) + i;                                                    \
        if (r < N) {                                                              \
            float o[8];                                                           \
            _Pragma("unroll")                                                     \
            for (int j = 0; j < 4; j++)                                           \
                asm("mov.b64 {%0,%1}, %2;" : "=f"(o[2*j]), "=f"(o[2*j+1]) : "l"(acc[i][j])); \
            uint4 pk;                                                             \
            pk.x = pk2(o[0], o[1]); pk.y = pk2(o[2], o[3]);                       \
            pk.z = pk2(o[4], o[5]); pk.w = pk2(o[6], o[7]);                       \
            *reinterpret_cast<uint4*>((HB) + (size_t)r * 64 + cx * 4) = pk;       \
        }                                                                         \
    }

// ---------------- GEMM: H = X @ W  (128-row tiles, X via cp.async double buffer) ----------------
// chunk = 32 k-floats (128 B/row); 4 chunks cover K=128
__global__ void __launch_bounds__(256, 2) k_gemm(const float* __restrict__ X,
                                                 const float* __restrict__ W,
                                                 __nv_bfloat162* __restrict__ Ho,
                                                 int N) {
    __shared__ float s_a[2][128 * APAD];     // 2 x 18.4 KB
    const int tid  = threadIdx.x;
    const int ry   = tid >> 4;               // 0..15
    const int cx   = tid & 15;               // 0..15
    const int tileRow0 = blockIdx.x * 128;
    const int row0 = tileRow0 + ry * 8;
    const int cb   = cx * 8;
    (void)cb;

    unsigned sbase[2];
    sbase[0] = (unsigned)__cvta_generic_to_shared(&s_a[0][0]);
    sbase[1] = (unsigned)__cvta_generic_to_shared(&s_a[1][0]);

#define COPY_CHUNK(BUF, C)                                                        \
    {                                                                             \
        _Pragma("unroll")                                                         \
        for (int t = 0; t < 4; t++) {                                             \
            int idx = t * 256 + tid;                                              \
            int crow = idx >> 3;                                                  \
            int seg  = idx & 7;                                                   \
            int grow = tileRow0 + crow;                                           \
            if (grow >= N) grow = N - 1;                                          \
            const char* src = (const char*)(X + (size_t)grow * D) + (C) * 128 + seg * 16; \
            unsigned dst = sbase[BUF] + (unsigned)(crow * APAD * 4 + seg * 16);   \
            asm volatile("cp.async.cg.shared.global [%0], [%1], 16;" :: "r"(dst), "l"(src)); \
        }                                                                         \
        asm volatile("cp.async.commit_group;");                                   \
    }

    unsigned long long acc[8][4];
#pragma unroll
    for (int i = 0; i < 8; i++)
#pragma unroll
        for (int j = 0; j < 4; j++) acc[i][j] = 0ull;

    const unsigned long long* wp = reinterpret_cast<const unsigned long long*>(W + cx * 8);

    COPY_CHUNK(0, 0)

    for (int c = 0; c < 4; c++) {
        if (c < 3) {
            COPY_CHUNK((c + 1) & 1, c + 1)
            asm volatile("cp.async.wait_group 1;");
        } else {
            asm volatile("cp.async.wait_group 0;");
        }
        __syncthreads();
        const float* ab = &s_a[c & 1][0];
#pragma unroll
        for (int kc8 = 0; kc8 < 8; kc8++) {
#define LOAD_A_P(i) (*reinterpret_cast<const float4*>(ab + (ry * 8 + (i)) * APAD + kc8 * 4))
            GEMM_KC_BODY(LOAD_A_P)
#undef LOAD_A_P
        }
        __syncthreads();   // all reads done before next copy overwrites the other buffer
    }
#undef COPY_CHUNK

    GEMM_STORE_BF16(Ho, row0)
}

// ---------------- gather helper: A[d] row (lane's 4 feats), self-term + edges ----------------
// H rows are bf16: 64 bf162 = 32 uint2 per row; lane owns uint2 #lane
__device__ __forceinline__ float4 gather_row(const __nv_bfloat162* __restrict__ Hb,
                                             int node, int lane) {
    const uint2* __restrict__ Hr = reinterpret_cast<const uint2*>(Hb);
    int beg = g_rowptr[node], end = g_rowptr[node + 1];
    float dv  = g_dinv[node];
    float dv2 = dv * dv;
    float4 h  = up4(__ldg(Hr + (size_t)node * 32 + lane));
    float4 acc = make_float4(h.x * dv2, h.y * dv2, h.z * dv2, h.w * dv2);

    int j = beg;
    for (; j + 4 <= end; j += 4) {
        int2 m0 = __ldg(&g_epack[j]);
        int2 m1 = __ldg(&g_epack[j + 1]);
        int2 m2 = __ldg(&g_epack[j + 2]);
        int2 m3 = __ldg(&g_epack[j + 3]);
        float4 h0 = up4(__ldg(Hr + (size_t)m0.x * 32 + lane));
        float4 h1 = up4(__ldg(Hr + (size_t)m1.x * 32 + lane));
        float4 h2 = up4(__ldg(Hr + (size_t)m2.x * 32 + lane));
        float4 h3 = up4(__ldg(Hr + (size_t)m3.x * 32 + lane));
        float w0 = __int_as_float(m0.y), w1 = __int_as_float(m1.y);
        float w2 = __int_as_float(m2.y), w3 = __int_as_float(m3.y);
        acc.x = fmaf(h0.x, w0, acc.x); acc.y = fmaf(h0.y, w0, acc.y);
        acc.z = fmaf(h0.z, w0, acc.z); acc.w = fmaf(h0.w, w0, acc.w);
        acc.x = fmaf(h1.x, w1, acc.x); acc.y = fmaf(h1.y, w1, acc.y);
        acc.z = fmaf(h1.z, w1, acc.z); acc.w = fmaf(h1.w, w1, acc.w);
        acc.x = fmaf(h2.x, w2, acc.x); acc.y = fmaf(h2.y, w2, acc.y);
        acc.z = fmaf(h2.z, w2, acc.z); acc.w = fmaf(h2.w, w2, acc.w);
        acc.x = fmaf(h3.x, w3, acc.x); acc.y = fmaf(h3.y, w3, acc.y);
        acc.z = fmaf(h3.z, w3, acc.z); acc.w = fmaf(h3.w, w3, acc.w);
    }
    for (; j < end; j++) {
        int2 m = __ldg(&g_epack[j]);
        float4 hh = up4(__ldg(Hr + (size_t)m.x * 32 + lane));
        float w = __int_as_float(m.y);
        acc.x = fmaf(hh.x, w, acc.x); acc.y = fmaf(hh.y, w, acc.y);
        acc.z = fmaf(hh.z, w, acc.z); acc.w = fmaf(hh.w, w, acc.w);
    }
    return acc;
}

// ---------------- fused: (gather1 + b1 + relu) -> smem (128x132) -> gemm2 -> H2(bf16) ----------------
__global__ void __launch_bounds__(256, 2) k_fused_ag(const __nv_bfloat162* __restrict__ Hb,
                                                     const float* __restrict__ bias,
                                                     const float* __restrict__ W,
                                                     __nv_bfloat162* __restrict__ H2b,
                                                     int N) {
    extern __shared__ float s_a[];       // 128 * 132 floats = 67584 B
    const int tid  = threadIdx.x;
    const int wid  = tid >> 5;
    const int lane = tid & 31;
    const int tile = blockIdx.x;

    float4 bb = reinterpret_cast<const float4*>(bias)[lane];

    // phase 1: 8 warps gather 16 nodes each into smem (bias+relu applied, fp32)
#pragma unroll 2
    for (int i = 0; i < 16; i++) {
        int lrow = wid * 16 + i;
        int node = tile * 128 + lrow;
        float4 v;
        if (node < N) {
            float4 acc4 = gather_row(Hb, node, lane);
            v = make_float4(fmaxf(acc4.x + bb.x, 0.0f), fmaxf(acc4.y + bb.y, 0.0f),
                            fmaxf(acc4.z + bb.z, 0.0f), fmaxf(acc4.w + bb.w, 0.0f));
        } else {
            v = make_float4(0.0f, 0.0f, 0.0f, 0.0f);
        }
        *reinterpret_cast<float4*>(&s_a[lrow * 132 + lane * 4]) = v;
    }
    __syncthreads();

    // phase 2: GEMM from smem
    const int ry    = tid >> 4;
    const int cx    = tid & 15;
    const int lrow0 = ry * 8;

    unsigned long long acc[8][4];
#pragma unroll
    for (int i = 0; i < 8; i++)
#pragma unroll
        for (int j = 0; j < 4; j++) acc[i][j] = 0ull;

    const unsigned long long* wp = reinterpret_cast<const unsigned long long*>(W + cx * 8);

#pragma unroll 2
    for (int kc = 0; kc < 32; kc++) {
#define LOAD_A_S(i) (*reinterpret_cast<const float4*>(&s_a[(lrow0 + (i)) * 132 + kc * 4]))
        GEMM_KC_BODY(LOAD_A_S)
#undef LOAD_A_S
    }

    const int row0 = tile * 128 + lrow0;
    GEMM_STORE_BF16(H2b, row0)
}

// ---------------- standalone gather (layer 2, no relu/bias; fp32 out) ----------------
__global__ void __launch_bounds__(256) k_gather2(const __nv_bfloat162* __restrict__ Hb,
                                                 float4* __restrict__ A4, int N) {
    int gw   = (blockIdx.x * blockDim.x + threadIdx.x) >> 5;
    int lane = threadIdx.x & 31;
    if (gw >= N) return;
    A4[(size_t)gw * 32 + lane] = gather_row(Hb, gw, lane);
}

// ---------------- fused global-mean-pool (+b2,relu) + MLP head ----------------
__global__ void __launch_bounds__(128) k_pool_mlp(const float* __restrict__ AGG,
                                                  const float* __restrict__ b2,
                                                  int Nnodes,
                                                  const float* __restrict__ Wm1,
                                                  const float* __restrict__ bm1,
                                                  const float* __restrict__ Wm2,
                                                  const float* __restrict__ bm2,
                                                  const float* __restrict__ Wm3,
                                                  const float* __restrict__ bm3,
                                                  float* __restrict__ out) {
    const int g = blockIdx.x;
    const int tid = threadIdx.x;
    __shared__ int sb[2];
    __shared__ float gs[128];
    __shared__ float a1[500];
    __shared__ float a2[100];
    __shared__ float red[128];

    if (tid < 2) {
        int target = g + tid;
        int lo = 0, hi = Nnodes;
        while (lo < hi) {
            int mid = (lo + hi) >> 1;
            if (g_batch[mid] < target) lo = mid + 1; else hi = mid;
        }
        sb[tid] = lo;
    }
    __syncthreads();
    int beg = sb[0], end = sb[1];
    int cnt = end - beg;

    float bb = b2[tid];
    float sum = 0.0f;
#pragma unroll 4
    for (int n = beg; n < end; n++)
        sum += fmaxf(AGG[(size_t)n * D + tid] + bb, 0.0f);
    gs[tid] = sum / (float)max(cnt, 1);
    __syncthreads();

    for (int o = tid; o < 500; o += 128) {
        float acc = bm1[o];
#pragma unroll 4
        for (int j = 0; j < 128; j++)
            acc = fmaf(gs[j], Wm1[j * 500 + o], acc);
        a1[o] = fmaxf(acc, 0.0f);
    }
    __syncthreads();

    if (tid < 100) {
        float acc = bm2[tid];
        for (int j = 0; j < 500; j++)
            acc = fmaf(a1[j], Wm2[j * 100 + tid], acc);
        a2[tid] = fmaxf(acc, 0.0f);
    }
    __syncthreads();

    red[tid] = (tid < 100) ? a2[tid] * Wm3[tid] : 0.0f;
    __syncthreads();
    for (int s = 64; s > 0; s >>= 1) {
        if (tid < s) red[tid] += red[tid + s];
        __syncthreads();
    }
    if (tid == 0) out[g] = red[0] + bm3[0];
}

// ---------------- launch ----------------
extern "C" void kernel_launch(void* const* d_in, const int* in_sizes, int n_in,
                              void* d_out, int out_size) {
    const float* x     = (const float*)d_in[0];
    const void*  edges = d_in[1];
    const void*  batch = d_in[2];
    const float* W1  = (const float*)d_in[3];
    const float* b1  = (const float*)d_in[4];
    const float* W2  = (const float*)d_in[5];
    const float* b2  = (const float*)d_in[6];
    const float* Wm1 = (const float*)d_in[7];
    const float* bm1 = (const float*)d_in[8];
    const float* Wm2 = (const float*)d_in[9];
    const float* bm2 = (const float*)d_in[10];
    const float* Wm3 = (const float*)d_in[11];
    const float* bm3 = (const float*)d_in[12];
    float* out = (float*)d_out;

    const int N = in_sizes[0] / D;
    const int E = in_sizes[1] / 2;
    const int G = out_size;

    __nv_bfloat162 *hA = nullptr, *hB = nullptr;
    float *bufC = nullptr;
    cudaGetSymbolAddress((void**)&hA, g_hA);
    cudaGetSymbolAddress((void**)&hB, g_hB);
    cudaGetSymbolAddress((void**)&bufC, g_bufC);

    const int tB = 256;
    const int nodeB   = (N + tB - 1) / tB;
    const int edgeB   = (E + tB - 1) / tB;
    const int scanNb  = (N + 1023) / 1024;
    const int tiles   = (N + 127) / 128;
    const int warpB   = (N * 32 + tB - 1) / tB;    // 1 warp/node
    const int smemAG  = 128 * 132 * sizeof(float); // 67584 B

    // idempotent, non-stream API: safe every call, no static guards
    cudaFuncSetAttribute(k_fused_ag, cudaFuncAttributeMaxDynamicSharedMemorySize, smemAG);

    // Fork infra: side stream + events, created per call, never destroyed
    cudaStream_t s2;
    cudaStreamCreateWithFlags(&s2, cudaStreamNonBlocking);
    cudaEvent_t evFork, evJoin;
    cudaEventCreateWithFlags(&evFork, cudaEventDisableTiming);
    cudaEventCreateWithFlags(&evJoin, cudaEventDisableTiming);

    // Fork point at entry of the capture stream: gemm1 depends on nothing.
    cudaEventRecord(evFork, 0);
    cudaStreamWaitEvent(s2, evFork, 0);

    // Branch B (main stream): CSR build chain
    k_init<<<nodeB + 1, tB>>>((const unsigned int*)edges, N, nodeB);        // 0
    k_prep<<<edgeB, tB>>>(edges, batch, E, N);                              // 1
    k_scan_block<<<scanNb, 1024>>>(N);                                      // 2
    // Branch A (side stream): layer1 GEMM — parallel branch in the graph
    k_gemm<<<tiles, tB, 0, s2>>>(x, W1, hA, N);                             // 3 (ncu slot)
    cudaEventRecord(evJoin, s2);
    // Branch B continues
    k_scan_add<<<nodeB, tB>>>(N, E, scanNb);                                // 4
    k_fill<<<edgeB, tB>>>(edges, E);                                        // 5

    // Join: fused gather1+gemm2 needs both hA and the CSR
    cudaStreamWaitEvent(0, evJoin, 0);
    k_fused_ag<<<tiles, tB, smemAG>>>(hA, b1, W2, hB, N);
    k_gather2<<<warpB, tB>>>(hB, (float4*)bufC, N);
    k_pool_mlp<<<G, 128>>>(bufC, b2, N, Wm1, bm1, Wm2, bm2, Wm3, bm3, out);
}